// round 2
// baseline (speedup 1.0000x reference)
#include <cuda_runtime.h>
#include <cstdint>
#include <cstddef>

// Problem constants
#define SEQ   2048
#define NB    4
#define NH    16
#define HD    64
#define MDIM  8192     // NB*SEQ
#define NDIM  1024
#define KDIM  1024

// ---------------- scratch (static device globals: allocation-free) -------------
__device__ float g_q[(size_t)NB * NH * SEQ * HD];   // [bh][s][d]
__device__ float g_k[(size_t)NB * NH * SEQ * HD];
__device__ float g_v[(size_t)NB * NH * SEQ * HD];
__device__ float g_o[(size_t)MDIM * NDIM];          // [b*SEQ+q][1024]
__device__ unsigned char g_mask8[(size_t)NB * SEQ * SEQ];
__device__ int g_mode;                              // 0=u8, 1=i32, 2=f32

// ---------------- mask dtype detection + conversion ---------------------------
__global__ void detect_mask_kernel(const unsigned int* __restrict__ w)
{
    __shared__ int s_not_i32, s_not_u8;
    if (threadIdx.x == 0) { s_not_i32 = 0; s_not_u8 = 0; }
    __syncthreads();
    int not_i32 = 0, not_u8 = 0;
    for (int i = threadIdx.x; i < 65536; i += 256) {
        unsigned v = w[i];
        unsigned b0 = v & 255u, b1 = (v >> 8) & 255u,
                 b2 = (v >> 16) & 255u, b3 = v >> 24;
        if ((b1 | b2 | b3) != 0u || b0 > 1u) not_i32 = 1;
        if (b0 > 1u || b1 > 1u || b2 > 1u || b3 > 1u) not_u8 = 1;
    }
    if (not_i32) atomicOr(&s_not_i32, 1);
    if (not_u8)  atomicOr(&s_not_u8, 1);
    __syncthreads();
    if (threadIdx.x == 0) {
        // int32 0/1 data also passes the u8 test, so check i32 first.
        // real u8 data fails the i32 test w.p. 1 - 2^-196608.
        g_mode = (!s_not_i32) ? 1 : ((!s_not_u8) ? 0 : 2);
    }
}

__global__ void convert_mask_kernel(const void* __restrict__ m,
                                    unsigned char* __restrict__ o)
{
    const int mode = g_mode;
    const size_t n4 = (size_t)NB * SEQ * SEQ / 4;
    for (size_t i = (size_t)blockIdx.x * blockDim.x + threadIdx.x; i < n4;
         i += (size_t)gridDim.x * blockDim.x) {
        uchar4 r;
        if (mode == 1) {
            int4 v = ((const int4*)m)[i];
            r = make_uchar4(v.x != 0, v.y != 0, v.z != 0, v.w != 0);
        } else if (mode == 2) {
            float4 v = ((const float4*)m)[i];
            r = make_uchar4(v.x != 0.f, v.y != 0.f, v.z != 0.f, v.w != 0.f);
        } else {
            uchar4 v = ((const uchar4*)m)[i];
            r = make_uchar4(v.x != 0, v.y != 0, v.z != 0, v.w != 0);
        }
        ((uchar4*)o)[i] = r;
    }
}

// ---------------- GEMM: C = A[M,K] @ W[N,K]^T  (M=8192, N=K=1024) -------------
#define BM 128
#define BN 128
#define BK 16
#define SP (BM + 4)

__global__ void __launch_bounds__(256, 2)
sgemm_nt(const float* __restrict__ A, const float* __restrict__ W,
         float* __restrict__ C, int mode)
{
    __shared__ float As[BK * SP];
    __shared__ float Bs[BK * SP];

    const int tid = threadIdx.x;
    const int tx  = tid & 15;
    const int ty  = tid >> 4;
    const int m0  = blockIdx.y * BM;
    const int n0  = blockIdx.x * BN;

    const int lr = tid >> 2;   // 0..63 (row within half-tile)
    const int kg = tid & 3;    // float4 group within BK

    float c[8][8];
#pragma unroll
    for (int i = 0; i < 8; i++)
#pragma unroll
        for (int j = 0; j < 8; j++) c[i][j] = 0.f;

    float4 pa[2], pb[2];

    // prologue: load k-tile 0 into regs, then smem (transposed)
#pragma unroll
    for (int it = 0; it < 2; it++) {
        int r = lr + it * 64;
        pa[it] = *(const float4*)(A + (size_t)(m0 + r) * KDIM + kg * 4);
        pb[it] = *(const float4*)(W + (size_t)(n0 + r) * KDIM + kg * 4);
    }
#pragma unroll
    for (int it = 0; it < 2; it++) {
        int r = lr + it * 64;
        As[(kg*4+0)*SP + r] = pa[it].x;
        As[(kg*4+1)*SP + r] = pa[it].y;
        As[(kg*4+2)*SP + r] = pa[it].z;
        As[(kg*4+3)*SP + r] = pa[it].w;
        Bs[(kg*4+0)*SP + r] = pb[it].x;
        Bs[(kg*4+1)*SP + r] = pb[it].y;
        Bs[(kg*4+2)*SP + r] = pb[it].z;
        Bs[(kg*4+3)*SP + r] = pb[it].w;
    }
    __syncthreads();

    const int NKT = KDIM / BK;
    for (int kt = 0; kt < NKT; kt++) {
        if (kt + 1 < NKT) {
            int k0 = (kt + 1) * BK;
#pragma unroll
            for (int it = 0; it < 2; it++) {
                int r = lr + it * 64;
                pa[it] = *(const float4*)(A + (size_t)(m0 + r) * KDIM + k0 + kg * 4);
                pb[it] = *(const float4*)(W + (size_t)(n0 + r) * KDIM + k0 + kg * 4);
            }
        }
#pragma unroll
        for (int kk = 0; kk < BK; kk++) {
            float a[8], b[8];
            *(float4*)&a[0] = *(const float4*)&As[kk*SP + ty*4];
            *(float4*)&a[4] = *(const float4*)&As[kk*SP + 64 + ty*4];
            *(float4*)&b[0] = *(const float4*)&Bs[kk*SP + tx*4];
            *(float4*)&b[4] = *(const float4*)&Bs[kk*SP + 64 + tx*4];
#pragma unroll
            for (int i = 0; i < 8; i++)
#pragma unroll
                for (int j = 0; j < 8; j++)
                    c[i][j] = fmaf(a[i], b[j], c[i][j]);
        }
        __syncthreads();
        if (kt + 1 < NKT) {
#pragma unroll
            for (int it = 0; it < 2; it++) {
                int r = lr + it * 64;
                As[(kg*4+0)*SP + r] = pa[it].x;
                As[(kg*4+1)*SP + r] = pa[it].y;
                As[(kg*4+2)*SP + r] = pa[it].z;
                As[(kg*4+3)*SP + r] = pa[it].w;
                Bs[(kg*4+0)*SP + r] = pb[it].x;
                Bs[(kg*4+1)*SP + r] = pb[it].y;
                Bs[(kg*4+2)*SP + r] = pb[it].z;
                Bs[(kg*4+3)*SP + r] = pb[it].w;
            }
            __syncthreads();
        }
    }

    // epilogue: rows in 4+4 quadrants, cols likewise
#pragma unroll
    for (int i = 0; i < 8; i++) {
        int mg = m0 + ty*4 + (i & 3) + ((i >> 2) * 64);
#pragma unroll
        for (int jg = 0; jg < 2; jg++) {
            int ng = n0 + tx*4 + jg*64;
            float4 v = make_float4(c[i][jg*4+0], c[i][jg*4+1], c[i][jg*4+2], c[i][jg*4+3]);
            if (mode == 0) {
                *(float4*)(C + (size_t)mg * NDIM + ng) = v;
            } else {
                int bb = mg >> 11, s = mg & 2047;
                int hh = ng >> 6,  d = ng & 63;
                *(float4*)(C + (((size_t)(bb*NH + hh) * SEQ + s) * HD + d)) = v;
            }
        }
    }
}

// ---------------- fused attention (SparseNormer, streaming) -------------------
#define AP 68   // smem row pitch (floats), 16B aligned
#define ASM_BYTES ((4*64*AP + 64)*4 + 64*64)

__global__ void __launch_bounds__(256, 2)
attn_kernel(const float* __restrict__ qb, const float* __restrict__ kb,
            const float* __restrict__ vb, const unsigned char* __restrict__ mask,
            const float* __restrict__ sn_bias, float* __restrict__ ob)
{
    extern __shared__ float sm[];
    float* Qs = sm;
    float* Ks = Qs + 64*AP;
    float* Vs = Ks + 64*AP;
    float* Ts = Vs + 64*AP;
    float* Rs = Ts + 64*AP;                       // [64] rowsums
    unsigned char* Ms = (unsigned char*)(Rs + 64); // [64][64] mask bytes

    const int bh  = blockIdx.y;       // 0..63
    const int b   = bh >> 4;
    const int h   = bh & 15;
    const int q0g = blockIdx.x * 64;
    const int tid = threadIdx.x;
    const int tx  = tid & 15;
    const int ty  = tid >> 4;
    const int q0  = ty * 4;
    const float bias = sn_bias[0];

    // load Q tile once
    const float* qsrc = qb + ((size_t)bh * SEQ + q0g) * HD;
#pragma unroll
    for (int it = 0; it < 4; it++) {
        int lin = tid + it * 256;
        int r = lin >> 4, dg = lin & 15;
        *(float4*)(Qs + r*AP + dg*4) = *(const float4*)(qsrc + (size_t)r*HD + dg*4);
    }

    float4 oacc[4];
    float  rs[4] = {0.f, 0.f, 0.f, 0.f};
#pragma unroll
    for (int i = 0; i < 4; i++) oacc[i] = make_float4(0.f, 0.f, 0.f, 0.f);

    const float* ksrc = kb + (size_t)bh * SEQ * HD;
    const float* vsrc = vb + (size_t)bh * SEQ * HD;
    const unsigned char* msrc = mask + ((size_t)b * SEQ + q0g) * SEQ;

    for (int kt = 0; kt < SEQ/64; kt++) {
        __syncthreads();   // protect Ks/Vs/Ts (prev iter phase2) and Qs (first iter)
        const float* kp = ksrc + (size_t)kt * 64 * HD;
        const float* vp = vsrc + (size_t)kt * 64 * HD;
#pragma unroll
        for (int it = 0; it < 4; it++) {
            int lin = tid + it * 256;
            int r = lin >> 4, dg = lin & 15;
            *(float4*)(Ks + r*AP + dg*4) = *(const float4*)(kp + (size_t)r*HD + dg*4);
            *(float4*)(Vs + r*AP + dg*4) = *(const float4*)(vp + (size_t)r*HD + dg*4);
        }
        {
            int r = tid >> 2, cg = tid & 3;
            *((uint4*)(Ms + r*64) + cg) =
                *((const uint4*)(msrc + (size_t)r*SEQ + kt*64) + cg);
        }
        __syncthreads();

        // phase 1: S = Q K^T for this tile; thread owns q0..q0+3 x {tx,tx+16,tx+32,tx+48}
        float s[4][4];
#pragma unroll
        for (int i = 0; i < 4; i++)
#pragma unroll
            for (int j = 0; j < 4; j++) s[i][j] = 0.f;

#pragma unroll 8
        for (int dg = 0; dg < 16; dg++) {
            float4 qv[4], kv[4];
#pragma unroll
            for (int i = 0; i < 4; i++) qv[i] = *(float4*)(Qs + (q0+i)*AP + dg*4);
#pragma unroll
            for (int j = 0; j < 4; j++) kv[j] = *(float4*)(Ks + (tx+16*j)*AP + dg*4);
#pragma unroll
            for (int i = 0; i < 4; i++)
#pragma unroll
                for (int j = 0; j < 4; j++) {
                    s[i][j] = fmaf(qv[i].x, kv[j].x, s[i][j]);
                    s[i][j] = fmaf(qv[i].y, kv[j].y, s[i][j]);
                    s[i][j] = fmaf(qv[i].z, kv[j].z, s[i][j]);
                    s[i][j] = fmaf(qv[i].w, kv[j].w, s[i][j]);
                }
        }

        // mask + bias + relu^2, rowsum (shfl over the 16 tx lanes), write T
#pragma unroll
        for (int i = 0; i < 4; i++) {
            float rsum = 0.f;
#pragma unroll
            for (int j = 0; j < 4; j++) {
                int kk = tx + 16*j;
                float t = fmaf(s[i][j], 0.125f, bias);   // /sqrt(64) then +bias
                t = fmaxf(t, 0.f);
                if (Ms[(q0+i)*64 + kk]) t = 0.f;         // masked -> relu(-1e32+b)=0
                t = t * t;
                Ts[(q0+i)*AP + kk] = t;
                rsum += t;
            }
            rsum += __shfl_xor_sync(0xffffffffu, rsum, 1);
            rsum += __shfl_xor_sync(0xffffffffu, rsum, 2);
            rsum += __shfl_xor_sync(0xffffffffu, rsum, 4);
            rsum += __shfl_xor_sync(0xffffffffu, rsum, 8);
            rs[i] += rsum;
        }
        __syncthreads();

        // phase 2: O += T * V  (thread owns q0..q0+3 rows x d-cols tx*4..tx*4+3)
#pragma unroll 4
        for (int k = 0; k < 64; k++) {
            float4 vv = *(float4*)(Vs + k*AP + tx*4);
#pragma unroll
            for (int i = 0; i < 4; i++) {
                float t = Ts[(q0+i)*AP + k];
                oacc[i].x = fmaf(t, vv.x, oacc[i].x);
                oacc[i].y = fmaf(t, vv.y, oacc[i].y);
                oacc[i].z = fmaf(t, vv.z, oacc[i].z);
                oacc[i].w = fmaf(t, vv.w, oacc[i].w);
            }
        }
    }

    if (tx == 0) {
#pragma unroll
        for (int i = 0; i < 4; i++) Rs[q0+i] = rs[i];
    }
    __syncthreads();

    // normalize + store directly in [B, NQ, HSIZE] layout
    float* od = ob + ((size_t)b * SEQ + q0g) * NDIM + h * HD;
#pragma unroll
    for (int i = 0; i < 4; i++) {
        float inv = 1.f / (Rs[q0+i] + 1e-32f);
        float4 o = oacc[i];
        o.x *= inv; o.y *= inv; o.z *= inv; o.w *= inv;
        *(float4*)(od + (size_t)(q0+i) * NDIM + tx*4) = o;
    }
}

// ---------------- launcher ----------------------------------------------------
extern "C" void kernel_launch(void* const* d_in, const int* in_sizes, int n_in,
                              void* d_out, int out_size)
{
    const float* iQ      = (const float*)d_in[0];
    const float* iK      = (const float*)d_in[1];
    const float* iV      = (const float*)d_in[2];
    const void*  mask    = d_in[3];
    const float* Wq      = (const float*)d_in[4];
    const float* Wk      = (const float*)d_in[5];
    const float* Wv      = (const float*)d_in[6];
    const float* Wo      = (const float*)d_in[7];
    const float* sn_bias = (const float*)d_in[8];
    float*       out     = (float*)d_out;

    float *gq, *gk, *gv, *go;
    unsigned char* gm;
    cudaGetSymbolAddress((void**)&gq, g_q);
    cudaGetSymbolAddress((void**)&gk, g_k);
    cudaGetSymbolAddress((void**)&gv, g_v);
    cudaGetSymbolAddress((void**)&go, g_o);
    cudaGetSymbolAddress((void**)&gm, g_mask8);

    cudaFuncSetAttribute(attn_kernel,
                         cudaFuncAttributeMaxDynamicSharedMemorySize, ASM_BYTES);

    dim3 gg(NDIM / BN, MDIM / BM);   // (8, 64)

    // mask dtype autodetect + conversion to u8 scratch
    detect_mask_kernel<<<1, 256>>>((const unsigned int*)mask);
    convert_mask_kernel<<<4096, 256>>>(mask, gm);

    sgemm_nt<<<gg, 256>>>(iQ, Wq, gq, 1);
    sgemm_nt<<<gg, 256>>>(iK, Wk, gk, 1);
    sgemm_nt<<<gg, 256>>>(iV, Wv, gv, 1);

    attn_kernel<<<dim3(SEQ / 64, NB * NH), 256, ASM_BYTES>>>(gq, gk, gv, gm,
                                                             sn_bias, go);

    sgemm_nt<<<gg, 256>>>(go, Wo, out, 0);
}

// round 4
// speedup vs baseline: 2.0480x; 2.0480x over previous
#include <cuda_runtime.h>
#include <cuda_bf16.h>
#include <cstdint>
#include <cstddef>

// Problem constants
#define SEQ   2048
#define NB    4
#define NH    16
#define HD    64
#define MDIM  8192     // NB*SEQ
#define NDIM  1024
#define KDIM  1024

// ---------------- scratch (static device globals: allocation-free) -------------
__device__ float g_q[(size_t)NB * NH * SEQ * HD];   // [bh][s][d]
__device__ float g_k[(size_t)NB * NH * SEQ * HD];
__device__ float g_v[(size_t)NB * NH * SEQ * HD];
__device__ float g_o[(size_t)MDIM * NDIM];          // [b*SEQ+q][1024]
__device__ unsigned char g_mask8[(size_t)NB * SEQ * SEQ];
__device__ int g_mode;                              // 0=u8, 1=i32, 2=f32

// ================= helpers =====================================================
__device__ __forceinline__ uint32_t smem_u32(const void* p) {
    uint32_t a;
    asm("{ .reg .u64 t; cvta.to.shared.u64 t, %1; cvt.u32.u64 %0, t; }"
        : "=r"(a) : "l"(p));
    return a;
}

__device__ __forceinline__ uint32_t pack_bf2(__nv_bfloat16 a, __nv_bfloat16 b) {
    __nv_bfloat162 t;
    t.x = a; t.y = b;
    return *(uint32_t*)&t;
}

// split fp32 -> (hi, lo) bf16 pair packs
__device__ __forceinline__ void cvt_hl4(float4 x, uint2& hp, uint2& lp) {
    __nv_bfloat16 h0 = __float2bfloat16(x.x), h1 = __float2bfloat16(x.y);
    __nv_bfloat16 h2 = __float2bfloat16(x.z), h3 = __float2bfloat16(x.w);
    hp = make_uint2(pack_bf2(h0, h1), pack_bf2(h2, h3));
    lp = make_uint2(
        pack_bf2(__float2bfloat16(x.x - __bfloat162float(h0)),
                 __float2bfloat16(x.y - __bfloat162float(h1))),
        pack_bf2(__float2bfloat16(x.z - __bfloat162float(h2)),
                 __float2bfloat16(x.w - __bfloat162float(h3))));
}

#define LDSM4(r, a) \
    asm volatile("ldmatrix.sync.aligned.m8n8.x4.shared.b16 {%0,%1,%2,%3}, [%4];" \
        : "=r"((r)[0]), "=r"((r)[1]), "=r"((r)[2]), "=r"((r)[3]) : "r"(a))

#define MMA_BF16(c, a, b0, b1) \
    asm volatile("mma.sync.aligned.m16n8k16.row.col.f32.bf16.bf16.f32 " \
        "{%0,%1,%2,%3}, {%4,%5,%6,%7}, {%8,%9}, {%0,%1,%2,%3};" \
        : "+f"((c)[0]), "+f"((c)[1]), "+f"((c)[2]), "+f"((c)[3]) \
        : "r"((a)[0]), "r"((a)[1]), "r"((a)[2]), "r"((a)[3]), "r"(b0), "r"(b1))

// ---------------- mask dtype detection + conversion ---------------------------
__global__ void detect_mask_kernel(const unsigned int* __restrict__ w)
{
    __shared__ int s_not_i32, s_not_u8;
    if (threadIdx.x == 0) { s_not_i32 = 0; s_not_u8 = 0; }
    __syncthreads();
    int not_i32 = 0, not_u8 = 0;
    for (int i = threadIdx.x; i < 65536; i += 256) {
        unsigned v = w[i];
        unsigned b0 = v & 255u, b1 = (v >> 8) & 255u,
                 b2 = (v >> 16) & 255u, b3 = v >> 24;
        if ((b1 | b2 | b3) != 0u || b0 > 1u) not_i32 = 1;
        if (b0 > 1u || b1 > 1u || b2 > 1u || b3 > 1u) not_u8 = 1;
    }
    if (not_i32) atomicOr(&s_not_i32, 1);
    if (not_u8)  atomicOr(&s_not_u8, 1);
    __syncthreads();
    if (threadIdx.x == 0)
        g_mode = (!s_not_i32) ? 1 : ((!s_not_u8) ? 0 : 2);
}

__global__ void convert_mask_kernel(const void* __restrict__ m,
                                    unsigned char* __restrict__ o)
{
    const int mode = g_mode;
    const size_t n4 = (size_t)NB * SEQ * SEQ / 4;
    for (size_t i = (size_t)blockIdx.x * blockDim.x + threadIdx.x; i < n4;
         i += (size_t)gridDim.x * blockDim.x) {
        uchar4 r;
        if (mode == 1) {
            int4 v = ((const int4*)m)[i];
            r = make_uchar4(v.x != 0, v.y != 0, v.z != 0, v.w != 0);
        } else if (mode == 2) {
            float4 v = ((const float4*)m)[i];
            r = make_uchar4(v.x != 0.f, v.y != 0.f, v.z != 0.f, v.w != 0.f);
        } else {
            uchar4 v = ((const uchar4*)m)[i];
            r = make_uchar4(v.x != 0, v.y != 0, v.z != 0, v.w != 0);
        }
        ((uchar4*)o)[i] = r;
    }
}

// ================= split-bf16 HMMA GEMM ========================================
// C[M,N] = A[M,K] @ W[N,K]^T  via  Ah*Wh + Ah*Wl + Al*Wh  (mma.m16n8k16.bf16)
#define GBK  32
#define NKT  (KDIM / GBK)     // 32
#define PADK 40               // bf16 pitch per row (80B, 16B-aligned, LDSM conflict-free)
#define T_AH 0
#define T_AL 10240
#define T_WH 20480
#define T_WL 30720
#define STG_B 40960
#define GSMEM (2 * STG_B)     // 80 KB

__global__ void __launch_bounds__(256, 1)
gemm_mma(const float* __restrict__ A, const float* __restrict__ W,
         float* __restrict__ C, int mode)
{
    extern __shared__ char smc[];
    const uint32_t smb = smem_u32(smc);
    const int tid  = threadIdx.x;
    const int lane = tid & 31, wid = tid >> 5;
    const int wm = wid & 3;        // 4 warp-rows of 32
    const int wn = wid >> 2;       // 2 warp-cols of 64
    const int m0 = blockIdx.y * 128, n0 = blockIdx.x * 128;

    const int lrow = tid >> 3;     // 0..31
    const int lcg  = tid & 7;      // float4 col group within 32-col stage
    const float* Ab = A + (size_t)(m0 + lrow) * KDIM + lcg * 4;
    const float* Wb = W + (size_t)(n0 + lrow) * KDIM + lcg * 4;

    float acc[2][8][4];
#pragma unroll
    for (int i = 0; i < 2; i++)
#pragma unroll
        for (int j = 0; j < 8; j++)
#pragma unroll
            for (int q = 0; q < 4; q++) acc[i][j][q] = 0.f;

    float4 ra[4], rw[4];

    // prologue: stage 0
#pragma unroll
    for (int i = 0; i < 4; i++) {
        ra[i] = *(const float4*)(Ab + (size_t)(32 * i) * KDIM);
        rw[i] = *(const float4*)(Wb + (size_t)(32 * i) * KDIM);
    }
#pragma unroll
    for (int i = 0; i < 4; i++) {
        int r = lrow + 32 * i;
        size_t off = (size_t)(r * PADK + lcg * 4) * 2;
        uint2 hp, lp;
        cvt_hl4(ra[i], hp, lp);
        *(uint2*)(smc + T_AH + off) = hp;
        *(uint2*)(smc + T_AL + off) = lp;
        cvt_hl4(rw[i], hp, lp);
        *(uint2*)(smc + T_WH + off) = hp;
        *(uint2*)(smc + T_WL + off) = lp;
    }
    __syncthreads();

    // ldmatrix lane offsets (bytes, within a tile base)
    const int a_r = lane & 15;
    const int a_c = (lane >> 4) << 3;
    const int b_r = (lane & 7) + ((lane >> 4) << 3);
    const int b_c = ((lane >> 3) & 1) << 3;

    for (int kt = 0; kt < NKT; kt++) {
        const int st = kt & 1;
        const uint32_t sb = smb + st * STG_B;

        if (kt + 1 < NKT) {
            int k0 = (kt + 1) * GBK;
#pragma unroll
            for (int i = 0; i < 4; i++) {
                ra[i] = *(const float4*)(Ab + (size_t)(32 * i) * KDIM + k0);
                rw[i] = *(const float4*)(Wb + (size_t)(32 * i) * KDIM + k0);
            }
        }

#pragma unroll
        for (int ks = 0; ks < 2; ks++) {
            uint32_t ah[2][4], al[2][4];
#pragma unroll
            for (int i = 0; i < 2; i++) {
                uint32_t off =
                    ((wm * 32 + i * 16 + a_r) * PADK + a_c + ks * 16) * 2;
                LDSM4(ah[i], sb + T_AH + off);
                LDSM4(al[i], sb + T_AL + off);
            }
            uint32_t bh[4][4], bl[4][4];
#pragma unroll
            for (int p = 0; p < 4; p++) {
                uint32_t off =
                    ((wn * 64 + p * 16 + b_r) * PADK + b_c + ks * 16) * 2;
                LDSM4(bh[p], sb + T_WH + off);
                LDSM4(bl[p], sb + T_WL + off);
            }
#pragma unroll
            for (int i = 0; i < 2; i++)
#pragma unroll
                for (int p = 0; p < 4; p++)
#pragma unroll
                    for (int hf = 0; hf < 2; hf++) {
                        int j = p * 2 + hf;
                        MMA_BF16(acc[i][j], ah[i], bh[p][2*hf], bh[p][2*hf+1]);
                        MMA_BF16(acc[i][j], ah[i], bl[p][2*hf], bl[p][2*hf+1]);
                        MMA_BF16(acc[i][j], al[i], bh[p][2*hf], bh[p][2*hf+1]);
                    }
        }
        __syncthreads();

        if (kt + 1 < NKT) {
            char* sn = smc + ((kt + 1) & 1) * STG_B;
#pragma unroll
            for (int i = 0; i < 4; i++) {
                int r = lrow + 32 * i;
                size_t off = (size_t)(r * PADK + lcg * 4) * 2;
                uint2 hp, lp;
                cvt_hl4(ra[i], hp, lp);
                *(uint2*)(sn + T_AH + off) = hp;
                *(uint2*)(sn + T_AL + off) = lp;
                cvt_hl4(rw[i], hp, lp);
                *(uint2*)(sn + T_WH + off) = hp;
                *(uint2*)(sn + T_WL + off) = lp;
            }
            __syncthreads();
        }
    }

    // epilogue
#pragma unroll
    for (int i = 0; i < 2; i++) {
#pragma unroll
        for (int j = 0; j < 8; j++) {
            int mrow = m0 + wm * 32 + i * 16 + (lane >> 2);
            int ncol = n0 + wn * 64 + j * 8 + (lane & 3) * 2;
#pragma unroll
            for (int hf = 0; hf < 2; hf++) {
                int m = mrow + hf * 8;
                float2 v = make_float2(acc[i][j][hf*2], acc[i][j][hf*2+1]);
                if (mode == 0) {
                    *(float2*)(C + (size_t)m * NDIM + ncol) = v;
                } else {
                    int bb = m >> 11, s = m & 2047;
                    int hh = ncol >> 6, d = ncol & 63;
                    *(float2*)(C + (((size_t)(bb*NH + hh) * SEQ + s) * HD + d)) = v;
                }
            }
        }
    }
}

// ---------------- fused attention (SparseNormer, streaming) -------------------
#define AP 68   // smem row pitch (floats), 16B aligned
#define ASM_BYTES ((4*64*AP + 64)*4 + 64*64)

__global__ void __launch_bounds__(256, 2)
attn_kernel(const float* __restrict__ qb, const float* __restrict__ kb,
            const float* __restrict__ vb, const unsigned char* __restrict__ mask,
            const float* __restrict__ sn_bias, float* __restrict__ ob)
{
    extern __shared__ float sm[];
    float* Qs = sm;
    float* Ks = Qs + 64*AP;
    float* Vs = Ks + 64*AP;
    float* Ts = Vs + 64*AP;
    float* Rs = Ts + 64*AP;                       // [64] rowsums
    unsigned char* Ms = (unsigned char*)(Rs + 64); // [64][64] mask bytes

    const int bh  = blockIdx.y;       // 0..63
    const int b   = bh >> 4;
    const int h   = bh & 15;
    const int q0g = blockIdx.x * 64;
    const int tid = threadIdx.x;
    const int tx  = tid & 15;
    const int ty  = tid >> 4;
    const int q0  = ty * 4;
    const float bias = sn_bias[0];

    const float* qsrc = qb + ((size_t)bh * SEQ + q0g) * HD;
#pragma unroll
    for (int it = 0; it < 4; it++) {
        int lin = tid + it * 256;
        int r = lin >> 4, dg = lin & 15;
        *(float4*)(Qs + r*AP + dg*4) = *(const float4*)(qsrc + (size_t)r*HD + dg*4);
    }

    float4 oacc[4];
    float  rs[4] = {0.f, 0.f, 0.f, 0.f};
#pragma unroll
    for (int i = 0; i < 4; i++) oacc[i] = make_float4(0.f, 0.f, 0.f, 0.f);

    const float* ksrc = kb + (size_t)bh * SEQ * HD;
    const float* vsrc = vb + (size_t)bh * SEQ * HD;
    const unsigned char* msrc = mask + ((size_t)b * SEQ + q0g) * SEQ;

    for (int kt = 0; kt < SEQ/64; kt++) {
        __syncthreads();
        const float* kp = ksrc + (size_t)kt * 64 * HD;
        const float* vp = vsrc + (size_t)kt * 64 * HD;
#pragma unroll
        for (int it = 0; it < 4; it++) {
            int lin = tid + it * 256;
            int r = lin >> 4, dg = lin & 15;
            *(float4*)(Ks + r*AP + dg*4) = *(const float4*)(kp + (size_t)r*HD + dg*4);
            *(float4*)(Vs + r*AP + dg*4) = *(const float4*)(vp + (size_t)r*HD + dg*4);
        }
        {
            int r = tid >> 2, cg = tid & 3;
            *((uint4*)(Ms + r*64) + cg) =
                *((const uint4*)(msrc + (size_t)r*SEQ + kt*64) + cg);
        }
        __syncthreads();

        float s[4][4];
#pragma unroll
        for (int i = 0; i < 4; i++)
#pragma unroll
            for (int j = 0; j < 4; j++) s[i][j] = 0.f;

#pragma unroll 8
        for (int dg = 0; dg < 16; dg++) {
            float4 qv[4], kv[4];
#pragma unroll
            for (int i = 0; i < 4; i++) qv[i] = *(float4*)(Qs + (q0+i)*AP + dg*4);
#pragma unroll
            for (int j = 0; j < 4; j++) kv[j] = *(float4*)(Ks + (tx+16*j)*AP + dg*4);
#pragma unroll
            for (int i = 0; i < 4; i++)
#pragma unroll
                for (int j = 0; j < 4; j++) {
                    s[i][j] = fmaf(qv[i].x, kv[j].x, s[i][j]);
                    s[i][j] = fmaf(qv[i].y, kv[j].y, s[i][j]);
                    s[i][j] = fmaf(qv[i].z, kv[j].z, s[i][j]);
                    s[i][j] = fmaf(qv[i].w, kv[j].w, s[i][j]);
                }
        }

#pragma unroll
        for (int i = 0; i < 4; i++) {
            float rsum = 0.f;
#pragma unroll
            for (int j = 0; j < 4; j++) {
                int kk = tx + 16*j;
                float t = fmaf(s[i][j], 0.125f, bias);
                t = fmaxf(t, 0.f);
                if (Ms[(q0+i)*64 + kk]) t = 0.f;
                t = t * t;
                Ts[(q0+i)*AP + kk] = t;
                rsum += t;
            }
            rsum += __shfl_xor_sync(0xffffffffu, rsum, 1);
            rsum += __shfl_xor_sync(0xffffffffu, rsum, 2);
            rsum += __shfl_xor_sync(0xffffffffu, rsum, 4);
            rsum += __shfl_xor_sync(0xffffffffu, rsum, 8);
            rs[i] += rsum;
        }
        __syncthreads();

#pragma unroll 4
        for (int k = 0; k < 64; k++) {
            float4 vv = *(float4*)(Vs + k*AP + tx*4);
#pragma unroll
            for (int i = 0; i < 4; i++) {
                float t = Ts[(q0+i)*AP + k];
                oacc[i].x = fmaf(t, vv.x, oacc[i].x);
                oacc[i].y = fmaf(t, vv.y, oacc[i].y);
                oacc[i].z = fmaf(t, vv.z, oacc[i].z);
                oacc[i].w = fmaf(t, vv.w, oacc[i].w);
            }
        }
    }

    if (tx == 0) {
#pragma unroll
        for (int i = 0; i < 4; i++) Rs[q0+i] = rs[i];
    }
    __syncthreads();

    float* od = ob + ((size_t)b * SEQ + q0g) * NDIM + h * HD;
#pragma unroll
    for (int i = 0; i < 4; i++) {
        float inv = 1.f / (Rs[q0+i] + 1e-32f);
        float4 o = oacc[i];
        o.x *= inv; o.y *= inv; o.z *= inv; o.w *= inv;
        *(float4*)(od + (size_t)(q0+i) * NDIM + tx*4) = o;
    }
}

// ---------------- launcher ----------------------------------------------------
extern "C" void kernel_launch(void* const* d_in, const int* in_sizes, int n_in,
                              void* d_out, int out_size)
{
    const float* iQ      = (const float*)d_in[0];
    const float* iK      = (const float*)d_in[1];
    const float* iV      = (const float*)d_in[2];
    const void*  mask    = d_in[3];
    const float* Wq      = (const float*)d_in[4];
    const float* Wk      = (const float*)d_in[5];
    const float* Wv      = (const float*)d_in[6];
    const float* Wo      = (const float*)d_in[7];
    const float* sn_bias = (const float*)d_in[8];
    float*       out     = (float*)d_out;

    float *gq, *gk, *gv, *go;
    unsigned char* gm;
    cudaGetSymbolAddress((void**)&gq, g_q);
    cudaGetSymbolAddress((void**)&gk, g_k);
    cudaGetSymbolAddress((void**)&gv, g_v);
    cudaGetSymbolAddress((void**)&go, g_o);
    cudaGetSymbolAddress((void**)&gm, g_mask8);

    cudaFuncSetAttribute(attn_kernel,
                         cudaFuncAttributeMaxDynamicSharedMemorySize, ASM_BYTES);
    cudaFuncSetAttribute(gemm_mma,
                         cudaFuncAttributeMaxDynamicSharedMemorySize, GSMEM);

    // mask dtype autodetect + conversion to u8 scratch
    detect_mask_kernel<<<1, 256>>>((const unsigned int*)mask);
    convert_mask_kernel<<<4096, 256>>>(mask, gm);

    dim3 gg(NDIM / 128, MDIM / 128);   // (8, 64)
    gemm_mma<<<gg, 256, GSMEM>>>(iQ, Wq, gq, 1);
    gemm_mma<<<gg, 256, GSMEM>>>(iK, Wk, gk, 1);
    gemm_mma<<<gg, 256, GSMEM>>>(iV, Wv, gv, 1);

    attn_kernel<<<dim3(SEQ / 64, NB * NH), 256, ASM_BYTES>>>(gq, gk, gv, gm,
                                                             sn_bias, go);

    gemm_mma<<<gg, 256, GSMEM>>>(go, Wo, out, 0);
}

// round 5
// speedup vs baseline: 4.0376x; 1.9715x over previous
#include <cuda_runtime.h>
#include <cuda_bf16.h>
#include <cstdint>
#include <cstddef>

// Problem constants
#define SEQ   2048
#define NB    4
#define NH    16
#define HD    64
#define MDIM  8192     // NB*SEQ
#define NDIM  1024
#define KDIM  1024

// ---------------- scratch (static device globals: allocation-free) -------------
__device__ float g_q[(size_t)NB * NH * SEQ * HD];   // [bh][s][d]
__device__ float g_k[(size_t)NB * NH * SEQ * HD];
__device__ float g_v[(size_t)NB * NH * SEQ * HD];
__device__ float g_o[(size_t)MDIM * NDIM];          // [b*SEQ+q][1024]
__device__ unsigned char g_mask8[(size_t)NB * SEQ * SEQ];
__device__ int g_mode;                              // 0=u8, 1=i32, 2=f32

// ================= helpers =====================================================
__device__ __forceinline__ uint32_t smem_u32(const void* p) {
    uint32_t a;
    asm("{ .reg .u64 t; cvta.to.shared.u64 t, %1; cvt.u32.u64 %0, t; }"
        : "=r"(a) : "l"(p));
    return a;
}

__device__ __forceinline__ uint32_t pack_bf2(__nv_bfloat16 a, __nv_bfloat16 b) {
    __nv_bfloat162 t;
    t.x = a; t.y = b;
    return *(uint32_t*)&t;
}

// split fp32 -> (hi, lo) bf16 pair packs
__device__ __forceinline__ void cvt_hl4(float4 x, uint2& hp, uint2& lp) {
    __nv_bfloat16 h0 = __float2bfloat16(x.x), h1 = __float2bfloat16(x.y);
    __nv_bfloat16 h2 = __float2bfloat16(x.z), h3 = __float2bfloat16(x.w);
    hp = make_uint2(pack_bf2(h0, h1), pack_bf2(h2, h3));
    lp = make_uint2(
        pack_bf2(__float2bfloat16(x.x - __bfloat162float(h0)),
                 __float2bfloat16(x.y - __bfloat162float(h1))),
        pack_bf2(__float2bfloat16(x.z - __bfloat162float(h2)),
                 __float2bfloat16(x.w - __bfloat162float(h3))));
}

#define LDSM4(r, a) \
    asm volatile("ldmatrix.sync.aligned.m8n8.x4.shared.b16 {%0,%1,%2,%3}, [%4];" \
        : "=r"((r)[0]), "=r"((r)[1]), "=r"((r)[2]), "=r"((r)[3]) : "r"(a))

#define LDSM4T(r, a) \
    asm volatile("ldmatrix.sync.aligned.m8n8.x4.trans.shared.b16 {%0,%1,%2,%3}, [%4];" \
        : "=r"((r)[0]), "=r"((r)[1]), "=r"((r)[2]), "=r"((r)[3]) : "r"(a))

#define MMA_BF16(c, a, b0, b1) \
    asm volatile("mma.sync.aligned.m16n8k16.row.col.f32.bf16.bf16.f32 " \
        "{%0,%1,%2,%3}, {%4,%5,%6,%7}, {%8,%9}, {%0,%1,%2,%3};" \
        : "+f"((c)[0]), "+f"((c)[1]), "+f"((c)[2]), "+f"((c)[3]) \
        : "r"((a)[0]), "r"((a)[1]), "r"((a)[2]), "r"((a)[3]), "r"(b0), "r"(b1))

// ---------------- mask dtype detection + conversion ---------------------------
__global__ void detect_mask_kernel(const unsigned int* __restrict__ w)
{
    __shared__ int s_not_i32, s_not_u8;
    if (threadIdx.x == 0) { s_not_i32 = 0; s_not_u8 = 0; }
    __syncthreads();
    int not_i32 = 0, not_u8 = 0;
    for (int i = threadIdx.x; i < 65536; i += 256) {
        unsigned v = w[i];
        unsigned b0 = v & 255u, b1 = (v >> 8) & 255u,
                 b2 = (v >> 16) & 255u, b3 = v >> 24;
        if ((b1 | b2 | b3) != 0u || b0 > 1u) not_i32 = 1;
        if (b0 > 1u || b1 > 1u || b2 > 1u || b3 > 1u) not_u8 = 1;
    }
    if (not_i32) atomicOr(&s_not_i32, 1);
    if (not_u8)  atomicOr(&s_not_u8, 1);
    __syncthreads();
    if (threadIdx.x == 0)
        g_mode = (!s_not_i32) ? 1 : ((!s_not_u8) ? 0 : 2);
}

__global__ void convert_mask_kernel(const void* __restrict__ m,
                                    unsigned char* __restrict__ o)
{
    const int mode = g_mode;
    const size_t n4 = (size_t)NB * SEQ * SEQ / 4;
    for (size_t i = (size_t)blockIdx.x * blockDim.x + threadIdx.x; i < n4;
         i += (size_t)gridDim.x * blockDim.x) {
        uchar4 r;
        if (mode == 1) {
            int4 v = ((const int4*)m)[i];
            r = make_uchar4(v.x != 0, v.y != 0, v.z != 0, v.w != 0);
        } else if (mode == 2) {
            float4 v = ((const float4*)m)[i];
            r = make_uchar4(v.x != 0.f, v.y != 0.f, v.z != 0.f, v.w != 0.f);
        } else {
            uchar4 v = ((const uchar4*)m)[i];
            r = make_uchar4(v.x != 0, v.y != 0, v.z != 0, v.w != 0);
        }
        ((uchar4*)o)[i] = r;
    }
}

// ================= split-bf16 HMMA GEMM ========================================
// C[M,N] = A[M,K] @ W[N,K]^T  via  Ah*Wh + Ah*Wl + Al*Wh  (mma.m16n8k16.bf16)
#define GBK  32
#define NKT  (KDIM / GBK)     // 32
#define PADK 40               // bf16 pitch per row (80B, 16B-aligned, LDSM conflict-free)
#define T_AH 0
#define T_AL 10240
#define T_WH 20480
#define T_WL 30720
#define STG_B 40960
#define GSMEM (2 * STG_B)     // 80 KB

__global__ void __launch_bounds__(256, 1)
gemm_mma(const float* __restrict__ A, const float* __restrict__ W,
         float* __restrict__ C, int mode)
{
    extern __shared__ char smc[];
    const uint32_t smb = smem_u32(smc);
    const int tid  = threadIdx.x;
    const int lane = tid & 31, wid = tid >> 5;
    const int wm = wid & 3;        // 4 warp-rows of 32
    const int wn = wid >> 2;       // 2 warp-cols of 64
    const int m0 = blockIdx.y * 128, n0 = blockIdx.x * 128;

    const int lrow = tid >> 3;     // 0..31
    const int lcg  = tid & 7;      // float4 col group within 32-col stage
    const float* Ab = A + (size_t)(m0 + lrow) * KDIM + lcg * 4;
    const float* Wb = W + (size_t)(n0 + lrow) * KDIM + lcg * 4;

    float acc[2][8][4];
#pragma unroll
    for (int i = 0; i < 2; i++)
#pragma unroll
        for (int j = 0; j < 8; j++)
#pragma unroll
            for (int q = 0; q < 4; q++) acc[i][j][q] = 0.f;

    float4 ra[4], rw[4];

#pragma unroll
    for (int i = 0; i < 4; i++) {
        ra[i] = *(const float4*)(Ab + (size_t)(32 * i) * KDIM);
        rw[i] = *(const float4*)(Wb + (size_t)(32 * i) * KDIM);
    }
#pragma unroll
    for (int i = 0; i < 4; i++) {
        int r = lrow + 32 * i;
        size_t off = (size_t)(r * PADK + lcg * 4) * 2;
        uint2 hp, lp;
        cvt_hl4(ra[i], hp, lp);
        *(uint2*)(smc + T_AH + off) = hp;
        *(uint2*)(smc + T_AL + off) = lp;
        cvt_hl4(rw[i], hp, lp);
        *(uint2*)(smc + T_WH + off) = hp;
        *(uint2*)(smc + T_WL + off) = lp;
    }
    __syncthreads();

    const int a_r = lane & 15;
    const int a_c = (lane >> 4) << 3;
    const int b_r = (lane & 7) + ((lane >> 4) << 3);
    const int b_c = ((lane >> 3) & 1) << 3;

    for (int kt = 0; kt < NKT; kt++) {
        const int st = kt & 1;
        const uint32_t sb = smb + st * STG_B;

        if (kt + 1 < NKT) {
            int k0 = (kt + 1) * GBK;
#pragma unroll
            for (int i = 0; i < 4; i++) {
                ra[i] = *(const float4*)(Ab + (size_t)(32 * i) * KDIM + k0);
                rw[i] = *(const float4*)(Wb + (size_t)(32 * i) * KDIM + k0);
            }
        }

#pragma unroll
        for (int ks = 0; ks < 2; ks++) {
            uint32_t ah[2][4], al[2][4];
#pragma unroll
            for (int i = 0; i < 2; i++) {
                uint32_t off =
                    ((wm * 32 + i * 16 + a_r) * PADK + a_c + ks * 16) * 2;
                LDSM4(ah[i], sb + T_AH + off);
                LDSM4(al[i], sb + T_AL + off);
            }
            uint32_t bh[4][4], bl[4][4];
#pragma unroll
            for (int p = 0; p < 4; p++) {
                uint32_t off =
                    ((wn * 64 + p * 16 + b_r) * PADK + b_c + ks * 16) * 2;
                LDSM4(bh[p], sb + T_WH + off);
                LDSM4(bl[p], sb + T_WL + off);
            }
#pragma unroll
            for (int i = 0; i < 2; i++)
#pragma unroll
                for (int p = 0; p < 4; p++)
#pragma unroll
                    for (int hf = 0; hf < 2; hf++) {
                        int j = p * 2 + hf;
                        MMA_BF16(acc[i][j], ah[i], bh[p][2*hf], bh[p][2*hf+1]);
                        MMA_BF16(acc[i][j], ah[i], bl[p][2*hf], bl[p][2*hf+1]);
                        MMA_BF16(acc[i][j], al[i], bh[p][2*hf], bh[p][2*hf+1]);
                    }
        }
        __syncthreads();

        if (kt + 1 < NKT) {
            char* sn = smc + ((kt + 1) & 1) * STG_B;
#pragma unroll
            for (int i = 0; i < 4; i++) {
                int r = lrow + 32 * i;
                size_t off = (size_t)(r * PADK + lcg * 4) * 2;
                uint2 hp, lp;
                cvt_hl4(ra[i], hp, lp);
                *(uint2*)(sn + T_AH + off) = hp;
                *(uint2*)(sn + T_AL + off) = lp;
                cvt_hl4(rw[i], hp, lp);
                *(uint2*)(sn + T_WH + off) = hp;
                *(uint2*)(sn + T_WL + off) = lp;
            }
            __syncthreads();
        }
    }

#pragma unroll
    for (int i = 0; i < 2; i++) {
#pragma unroll
        for (int j = 0; j < 8; j++) {
            int mrow = m0 + wm * 32 + i * 16 + (lane >> 2);
            int ncol = n0 + wn * 64 + j * 8 + (lane & 3) * 2;
#pragma unroll
            for (int hf = 0; hf < 2; hf++) {
                int m = mrow + hf * 8;
                float2 v = make_float2(acc[i][j][hf*2], acc[i][j][hf*2+1]);
                if (mode == 0) {
                    *(float2*)(C + (size_t)m * NDIM + ncol) = v;
                } else {
                    int bb = m >> 11, s = m & 2047;
                    int hh = ncol >> 6, d = ncol & 63;
                    *(float2*)(C + (((size_t)(bb*NH + hh) * SEQ + s) * HD + d)) = v;
                }
            }
        }
    }
}

// ================= HMMA fused attention (SparseNormer) =========================
// CTA: 128 q-rows x one (b,h). 8 warps x 16 q-rows. K/V streamed in 64-row tiles.
#define APCH 72                       // bf16 smem pitch (144B: 16B-aligned, LDSM conflict-free)
#define A_QH 0
#define A_QL (A_QH + 128 * APCH * 2)  // 18432
#define A_KH (A_QL + 128 * APCH * 2)  // 36864
#define A_KL (A_KH + 64 * APCH * 2)   // 46080
#define A_VH (A_KL + 64 * APCH * 2)   // 55296
#define A_VL (A_VH + 64 * APCH * 2)   // 64512
#define A_MS (A_VL + 64 * APCH * 2)   // 73728
#define A_BYTES (A_MS + 128 * 64)     // 81920

__global__ void __launch_bounds__(256, 2)
attn_mma(const float* __restrict__ qb, const float* __restrict__ kb,
         const float* __restrict__ vb, const unsigned char* __restrict__ mask,
         const float* __restrict__ sn_bias, float* __restrict__ ob)
{
    extern __shared__ char sm[];
    const uint32_t smb = smem_u32(sm);
    const int tid  = threadIdx.x;
    const int lane = tid & 31, wid = tid >> 5;   // wid = q-row group (16 rows)
    const int bh = blockIdx.y;
    const int b = bh >> 4, h = bh & 15;
    const int q0g = blockIdx.x * 128;
    const float bias = sn_bias[0];

    // load + split Q tile [128 x 64]
    const float* qsrc = qb + ((size_t)bh * SEQ + q0g) * HD;
#pragma unroll
    for (int i = 0; i < 8; i++) {
        int lin = tid + i * 256;
        int row = lin >> 4, c4 = lin & 15;
        float4 x = *(const float4*)(qsrc + (size_t)row * HD + c4 * 4);
        uint2 hp, lp;
        cvt_hl4(x, hp, lp);
        size_t off = (size_t)(row * APCH + c4 * 4) * 2;
        *(uint2*)(sm + A_QH + off) = hp;
        *(uint2*)(sm + A_QL + off) = lp;
    }

    float oacc[8][4];
#pragma unroll
    for (int j = 0; j < 8; j++)
#pragma unroll
        for (int e = 0; e < 4; e++) oacc[j][e] = 0.f;
    float rsum0 = 0.f, rsum1 = 0.f;

    const float* ksrc = kb + (size_t)bh * SEQ * HD;
    const float* vsrc = vb + (size_t)bh * SEQ * HD;
    const unsigned char* msrc = mask + ((size_t)b * SEQ + q0g) * SEQ;

    // ldmatrix lane offsets
    const int a_r = lane & 15;
    const int a_c = (lane >> 4) << 3;
    const int b_r = (lane & 7) + ((lane >> 4) << 3);
    const int b_c = ((lane >> 3) & 1) << 3;
    const int v_r = ((lane >> 3) & 1) * 8 + (lane & 7);   // trans: k-row within 16
    const int v_c = (lane >> 4) << 3;                     // trans: n(d) offset

    const int mrow0 = wid * 16 + (lane >> 2);             // CTA-local q row (c0/c1)

    for (int kt = 0; kt < SEQ / 64; kt++) {
        __syncthreads();
        // stage K, V (64x64) + mask (128x64)
        const float* kp = ksrc + (size_t)kt * 64 * HD;
        const float* vp = vsrc + (size_t)kt * 64 * HD;
#pragma unroll
        for (int i = 0; i < 4; i++) {
            int lin = tid + i * 256;
            int row = lin >> 4, c4 = lin & 15;
            size_t off = (size_t)(row * APCH + c4 * 4) * 2;
            uint2 hp, lp;
            cvt_hl4(*(const float4*)(kp + (size_t)row * HD + c4 * 4), hp, lp);
            *(uint2*)(sm + A_KH + off) = hp;
            *(uint2*)(sm + A_KL + off) = lp;
            cvt_hl4(*(const float4*)(vp + (size_t)row * HD + c4 * 4), hp, lp);
            *(uint2*)(sm + A_VH + off) = hp;
            *(uint2*)(sm + A_VL + off) = lp;
        }
#pragma unroll
        for (int i = 0; i < 2; i++) {
            int lin = tid + i * 256;
            int q = lin >> 2, kg = lin & 3;
            *((uint4*)(sm + A_MS + q * 64) + kg) =
                *((const uint4*)(msrc + (size_t)q * SEQ + kt * 64) + kg);
        }
        __syncthreads();

        // ---- S = Q K^T (per warp: 16 q x 64 k), chunked by 16 k-rows --------
        uint32_t aph[4][4], apl[4][4];   // T fragments (A-operand for T*V)
#pragma unroll
        for (int nc = 0; nc < 4; nc++) {
            float sc[2][4];
#pragma unroll
            for (int hf = 0; hf < 2; hf++)
#pragma unroll
                for (int e = 0; e < 4; e++) sc[hf][e] = 0.f;

#pragma unroll
            for (int dc = 0; dc < 4; dc++) {
                uint32_t qh[4], ql[4], kh[4], kl[4];
                uint32_t qa = smb + A_QH +
                    ((wid * 16 + a_r) * APCH + dc * 16 + a_c) * 2;
                LDSM4(qh, qa);
                LDSM4(ql, qa + (A_QL - A_QH));
                uint32_t ka = smb + A_KH +
                    ((nc * 16 + b_r) * APCH + dc * 16 + b_c) * 2;
                LDSM4(kh, ka);
                LDSM4(kl, ka + (A_KL - A_KH));
#pragma unroll
                for (int hf = 0; hf < 2; hf++) {
                    MMA_BF16(sc[hf], qh, kh[2*hf], kh[2*hf+1]);
                    MMA_BF16(sc[hf], qh, kl[2*hf], kl[2*hf+1]);
                    MMA_BF16(sc[hf], ql, kh[2*hf], kh[2*hf+1]);
                }
            }

            // mask + bias + relu^2, rowsum, split to bf16 A-fragments
#pragma unroll
            for (int hf = 0; hf < 2; hf++) {
                int kcol = nc * 16 + hf * 8 + 2 * (lane & 3);
                uchar2 m0 = *(const uchar2*)(sm + A_MS + mrow0 * 64 + kcol);
                uchar2 m1 = *(const uchar2*)(sm + A_MS + (mrow0 + 8) * 64 + kcol);
                float t0 = fmaxf(fmaf(sc[hf][0], 0.125f, bias), 0.f);
                float t1 = fmaxf(fmaf(sc[hf][1], 0.125f, bias), 0.f);
                float t2 = fmaxf(fmaf(sc[hf][2], 0.125f, bias), 0.f);
                float t3 = fmaxf(fmaf(sc[hf][3], 0.125f, bias), 0.f);
                if (m0.x) t0 = 0.f;
                if (m0.y) t1 = 0.f;
                if (m1.x) t2 = 0.f;
                if (m1.y) t3 = 0.f;
                t0 *= t0; t1 *= t1; t2 *= t2; t3 *= t3;
                rsum0 += t0 + t1;
                rsum1 += t2 + t3;
                __nv_bfloat16 h0 = __float2bfloat16(t0), h1 = __float2bfloat16(t1);
                __nv_bfloat16 h2 = __float2bfloat16(t2), h3 = __float2bfloat16(t3);
                aph[nc][2*hf + 0] = pack_bf2(h0, h1);
                aph[nc][2*hf + 1] = pack_bf2(h2, h3);
                apl[nc][2*hf + 0] = pack_bf2(
                    __float2bfloat16(t0 - __bfloat162float(h0)),
                    __float2bfloat16(t1 - __bfloat162float(h1)));
                apl[nc][2*hf + 1] = pack_bf2(
                    __float2bfloat16(t2 - __bfloat162float(h2)),
                    __float2bfloat16(t3 - __bfloat162float(h3)));
            }
        }

        // ---- O += T * V  (B from [k][d] tile via ldmatrix.trans) ------------
#pragma unroll
        for (int kc = 0; kc < 4; kc++) {
#pragma unroll
            for (int dch = 0; dch < 4; dch++) {
                uint32_t vh[4], vl[4];
                uint32_t va = smb + A_VH +
                    ((kc * 16 + v_r) * APCH + dch * 16 + v_c) * 2;
                LDSM4T(vh, va);
                LDSM4T(vl, va + (A_VL - A_VH));
#pragma unroll
                for (int hf = 0; hf < 2; hf++) {
                    int j = dch * 2 + hf;
                    MMA_BF16(oacc[j], aph[kc], vh[2*hf], vh[2*hf+1]);
                    MMA_BF16(oacc[j], apl[kc], vh[2*hf], vh[2*hf+1]);
                    MMA_BF16(oacc[j], aph[kc], vl[2*hf], vl[2*hf+1]);
                }
            }
        }
    }

    // rowsum reduce across the 4 lanes sharing each row (lane&3 group)
    rsum0 += __shfl_xor_sync(0xffffffffu, rsum0, 1);
    rsum0 += __shfl_xor_sync(0xffffffffu, rsum0, 2);
    rsum1 += __shfl_xor_sync(0xffffffffu, rsum1, 1);
    rsum1 += __shfl_xor_sync(0xffffffffu, rsum1, 2);
    const float inv0 = 1.f / (rsum0 + 1e-32f);
    const float inv1 = 1.f / (rsum1 + 1e-32f);

    // store O into [B, NQ, HSIZE] layout
    const int qr0 = q0g + mrow0;
#pragma unroll
    for (int j = 0; j < 8; j++) {
        int d = h * HD + j * 8 + 2 * (lane & 3);
        *(float2*)(ob + (size_t)(b * SEQ + qr0) * NDIM + d) =
            make_float2(oacc[j][0] * inv0, oacc[j][1] * inv0);
        *(float2*)(ob + (size_t)(b * SEQ + qr0 + 8) * NDIM + d) =
            make_float2(oacc[j][2] * inv1, oacc[j][3] * inv1);
    }
}

// ---------------- launcher ----------------------------------------------------
extern "C" void kernel_launch(void* const* d_in, const int* in_sizes, int n_in,
                              void* d_out, int out_size)
{
    const float* iQ      = (const float*)d_in[0];
    const float* iK      = (const float*)d_in[1];
    const float* iV      = (const float*)d_in[2];
    const void*  mask    = d_in[3];
    const float* Wq      = (const float*)d_in[4];
    const float* Wk      = (const float*)d_in[5];
    const float* Wv      = (const float*)d_in[6];
    const float* Wo      = (const float*)d_in[7];
    const float* sn_bias = (const float*)d_in[8];
    float*       out     = (float*)d_out;

    float *gq, *gk, *gv, *go;
    unsigned char* gm;
    cudaGetSymbolAddress((void**)&gq, g_q);
    cudaGetSymbolAddress((void**)&gk, g_k);
    cudaGetSymbolAddress((void**)&gv, g_v);
    cudaGetSymbolAddress((void**)&go, g_o);
    cudaGetSymbolAddress((void**)&gm, g_mask8);

    cudaFuncSetAttribute(gemm_mma,
                         cudaFuncAttributeMaxDynamicSharedMemorySize, GSMEM);
    cudaFuncSetAttribute(attn_mma,
                         cudaFuncAttributeMaxDynamicSharedMemorySize, A_BYTES);

    // mask dtype autodetect + conversion to u8 scratch
    detect_mask_kernel<<<1, 256>>>((const unsigned int*)mask);
    convert_mask_kernel<<<4096, 256>>>(mask, gm);

    dim3 gg(NDIM / 128, MDIM / 128);   // (8, 64)
    gemm_mma<<<gg, 256, GSMEM>>>(iQ, Wq, gq, 1);
    gemm_mma<<<gg, 256, GSMEM>>>(iK, Wk, gk, 1);
    gemm_mma<<<gg, 256, GSMEM>>>(iV, Wv, gv, 1);

    attn_mma<<<dim3(SEQ / 128, NB * NH), 256, A_BYTES>>>(gq, gk, gv, gm,
                                                         sn_bias, go);

    gemm_mma<<<gg, 256, GSMEM>>>(go, Wo, out, 0);
}

// round 6
// speedup vs baseline: 4.2893x; 1.0623x over previous
#include <cuda_runtime.h>
#include <cuda_bf16.h>
#include <cstdint>
#include <cstddef>

// Problem constants
#define SEQ   2048
#define NB    4
#define NH    16
#define HD    64
#define MDIM  8192     // NB*SEQ
#define NDIM  1024
#define KDIM  1024

// ---------------- scratch (static device globals: allocation-free) -------------
__device__ __nv_bfloat16 g_xh[(size_t)MDIM * KDIM];  // A hi (inputs / attn O)
__device__ __nv_bfloat16 g_xl[(size_t)MDIM * KDIM];  // A lo
__device__ __nv_bfloat16 g_wh[(size_t)NDIM * KDIM];  // W hi (reused per gemm)
__device__ __nv_bfloat16 g_wl[(size_t)NDIM * KDIM];  // W lo
__device__ __nv_bfloat16 g_qh[(size_t)NB * NH * SEQ * HD];
__device__ __nv_bfloat16 g_ql[(size_t)NB * NH * SEQ * HD];
__device__ __nv_bfloat16 g_kh[(size_t)NB * NH * SEQ * HD];
__device__ __nv_bfloat16 g_kl[(size_t)NB * NH * SEQ * HD];
__device__ __nv_bfloat16 g_vh[(size_t)NB * NH * SEQ * HD];
__device__ __nv_bfloat16 g_vl[(size_t)NB * NH * SEQ * HD];
__device__ unsigned char g_mask8[(size_t)NB * SEQ * SEQ];
__device__ int g_mode;                              // 0=u8, 1=i32, 2=f32

// ================= helpers =====================================================
__device__ __forceinline__ uint32_t smem_u32(const void* p) {
    uint32_t a;
    asm("{ .reg .u64 t; cvta.to.shared.u64 t, %1; cvt.u32.u64 %0, t; }"
        : "=r"(a) : "l"(p));
    return a;
}

__device__ __forceinline__ uint32_t pack_bf2(__nv_bfloat16 a, __nv_bfloat16 b) {
    __nv_bfloat162 t;
    t.x = a; t.y = b;
    return *(uint32_t*)&t;
}

// split fp32 -> (hi, lo) bf16 pair packs
__device__ __forceinline__ void cvt_hl4(float4 x, uint2& hp, uint2& lp) {
    __nv_bfloat16 h0 = __float2bfloat16(x.x), h1 = __float2bfloat16(x.y);
    __nv_bfloat16 h2 = __float2bfloat16(x.z), h3 = __float2bfloat16(x.w);
    hp = make_uint2(pack_bf2(h0, h1), pack_bf2(h2, h3));
    lp = make_uint2(
        pack_bf2(__float2bfloat16(x.x - __bfloat162float(h0)),
                 __float2bfloat16(x.y - __bfloat162float(h1))),
        pack_bf2(__float2bfloat16(x.z - __bfloat162float(h2)),
                 __float2bfloat16(x.w - __bfloat162float(h3))));
}

__device__ __forceinline__ void cvt_hl2(float x0, float x1,
                                        uint32_t& hp, uint32_t& lp) {
    __nv_bfloat16 h0 = __float2bfloat16(x0), h1 = __float2bfloat16(x1);
    hp = pack_bf2(h0, h1);
    lp = pack_bf2(__float2bfloat16(x0 - __bfloat162float(h0)),
                  __float2bfloat16(x1 - __bfloat162float(h1)));
}

#define LDSM4(r, a) \
    asm volatile("ldmatrix.sync.aligned.m8n8.x4.shared.b16 {%0,%1,%2,%3}, [%4];" \
        : "=r"((r)[0]), "=r"((r)[1]), "=r"((r)[2]), "=r"((r)[3]) : "r"(a))

#define LDSM4T(r, a) \
    asm volatile("ldmatrix.sync.aligned.m8n8.x4.trans.shared.b16 {%0,%1,%2,%3}, [%4];" \
        : "=r"((r)[0]), "=r"((r)[1]), "=r"((r)[2]), "=r"((r)[3]) : "r"(a))

#define MMA_BF16(c, a, b0, b1) \
    asm volatile("mma.sync.aligned.m16n8k16.row.col.f32.bf16.bf16.f32 " \
        "{%0,%1,%2,%3}, {%4,%5,%6,%7}, {%8,%9}, {%0,%1,%2,%3};" \
        : "+f"((c)[0]), "+f"((c)[1]), "+f"((c)[2]), "+f"((c)[3]) \
        : "r"((a)[0]), "r"((a)[1]), "r"((a)[2]), "r"((a)[3]), "r"(b0), "r"(b1))

#define CP_A16(dst, src) \
    asm volatile("cp.async.cg.shared.global [%0], [%1], 16;" :: "r"(dst), "l"(src))
#define CP_COMMIT() asm volatile("cp.async.commit_group;" ::: "memory")
#define CP_WAIT1()  asm volatile("cp.async.wait_group 1;" ::: "memory")

// ---------------- mask dtype detection + conversion ---------------------------
__global__ void detect_mask_kernel(const unsigned int* __restrict__ w)
{
    __shared__ int s_not_i32, s_not_u8;
    if (threadIdx.x == 0) { s_not_i32 = 0; s_not_u8 = 0; }
    __syncthreads();
    int not_i32 = 0, not_u8 = 0;
    for (int i = threadIdx.x; i < 65536; i += 256) {
        unsigned v = w[i];
        unsigned b0 = v & 255u, b1 = (v >> 8) & 255u,
                 b2 = (v >> 16) & 255u, b3 = v >> 24;
        if ((b1 | b2 | b3) != 0u || b0 > 1u) not_i32 = 1;
        if (b0 > 1u || b1 > 1u || b2 > 1u || b3 > 1u) not_u8 = 1;
    }
    if (not_i32) atomicOr(&s_not_i32, 1);
    if (not_u8)  atomicOr(&s_not_u8, 1);
    __syncthreads();
    if (threadIdx.x == 0)
        g_mode = (!s_not_i32) ? 1 : ((!s_not_u8) ? 0 : 2);
}

__global__ void convert_mask_kernel(const void* __restrict__ m,
                                    unsigned char* __restrict__ o)
{
    const int mode = g_mode;
    const size_t n4 = (size_t)NB * SEQ * SEQ / 4;
    for (size_t i = (size_t)blockIdx.x * blockDim.x + threadIdx.x; i < n4;
         i += (size_t)gridDim.x * blockDim.x) {
        uchar4 r;
        if (mode == 1) {
            int4 v = ((const int4*)m)[i];
            r = make_uchar4(v.x != 0, v.y != 0, v.z != 0, v.w != 0);
        } else if (mode == 2) {
            float4 v = ((const float4*)m)[i];
            r = make_uchar4(v.x != 0.f, v.y != 0.f, v.z != 0.f, v.w != 0.f);
        } else {
            uchar4 v = ((const uchar4*)m)[i];
            r = make_uchar4(v.x != 0, v.y != 0, v.z != 0, v.w != 0);
        }
        ((uchar4*)o)[i] = r;
    }
}

// ---------------- fp32 -> (hi, lo) bf16 streaming split ------------------------
__global__ void convert_hl(const float4* __restrict__ in,
                           uint2* __restrict__ hi, uint2* __restrict__ lo,
                           size_t n4)
{
    for (size_t i = (size_t)blockIdx.x * blockDim.x + threadIdx.x; i < n4;
         i += (size_t)gridDim.x * blockDim.x) {
        uint2 h, l;
        cvt_hl4(in[i], h, l);
        hi[i] = h;
        lo[i] = l;
    }
}

// ================= split-bf16 HMMA GEMM (cp.async pipeline) ====================
// C[M,N] = A[M,K] @ W[N,K]^T  via  Ah*Wh + Ah*Wl + Al*Wh  (mma.m16n8k16.bf16)
#define GBK  32
#define NKT  (KDIM / GBK)     // 32
#define PADK 40               // bf16 pitch per row (80B, 16B-aligned, LDSM conflict-free)
#define T_AH 0
#define T_AL 10240
#define T_WH 20480
#define T_WL 30720
#define STG_B 40960
#define GSMEM (2 * STG_B)     // 80 KB

__global__ void __launch_bounds__(256, 2)
gemm_bf(const __nv_bfloat16* __restrict__ Ah, const __nv_bfloat16* __restrict__ Al,
        const __nv_bfloat16* __restrict__ Wh, const __nv_bfloat16* __restrict__ Wl,
        float* __restrict__ Cf,
        __nv_bfloat16* __restrict__ Ch, __nv_bfloat16* __restrict__ Cl,
        int mode)
{
    extern __shared__ char smc[];
    const uint32_t smb = smem_u32(smc);
    const int tid  = threadIdx.x;
    const int lane = tid & 31, wid = tid >> 5;
    const int wm = wid & 3;        // 4 warp-rows of 32
    const int wn = wid >> 2;       // 2 warp-cols of 64
    const int m0 = blockIdx.y * 128, n0 = blockIdx.x * 128;

    const int row0 = tid >> 2;     // 0..63
    const int ch   = tid & 3;      // 16B chunk (8 bf16) within 32-col stage

    float acc[2][8][4];
#pragma unroll
    for (int i = 0; i < 2; i++)
#pragma unroll
        for (int j = 0; j < 8; j++)
#pragma unroll
            for (int q = 0; q < 4; q++) acc[i][j][q] = 0.f;

    // cp.async stage issue (commit always, loads only if kt valid)
    auto issue = [&](int kt) {
        if (kt < NKT) {
            const int k0 = kt * GBK;
            const uint32_t sb = smb + (kt & 1) * STG_B;
#pragma unroll
            for (int half = 0; half < 2; half++) {
                int r = row0 + half * 64;
                uint32_t doff = (uint32_t)(r * PADK + ch * 8) * 2;
                const size_t asrc = (size_t)(m0 + r) * KDIM + k0 + ch * 8;
                const size_t wsrc = (size_t)(n0 + r) * KDIM + k0 + ch * 8;
                CP_A16(sb + T_AH + doff, Ah + asrc);
                CP_A16(sb + T_AL + doff, Al + asrc);
                CP_A16(sb + T_WH + doff, Wh + wsrc);
                CP_A16(sb + T_WL + doff, Wl + wsrc);
            }
        }
        CP_COMMIT();
    };

    issue(0);
    issue(1);
    CP_WAIT1();
    __syncthreads();

    const int a_r = lane & 15;
    const int a_c = (lane >> 4) << 3;
    const int b_r = (lane & 7) + ((lane >> 4) << 3);
    const int b_c = ((lane >> 3) & 1) << 3;

    for (int kt = 0; kt < NKT; kt++) {
        const uint32_t sb = smb + (kt & 1) * STG_B;

#pragma unroll
        for (int ks = 0; ks < 2; ks++) {
            uint32_t ah[2][4], al[2][4];
#pragma unroll
            for (int i = 0; i < 2; i++) {
                uint32_t off =
                    ((wm * 32 + i * 16 + a_r) * PADK + a_c + ks * 16) * 2;
                LDSM4(ah[i], sb + T_AH + off);
                LDSM4(al[i], sb + T_AL + off);
            }
#pragma unroll
            for (int p = 0; p < 4; p++) {
                uint32_t bh[4], bl[4];
                uint32_t off =
                    ((wn * 64 + p * 16 + b_r) * PADK + b_c + ks * 16) * 2;
                LDSM4(bh, sb + T_WH + off);
                LDSM4(bl, sb + T_WL + off);
#pragma unroll
                for (int i = 0; i < 2; i++)
#pragma unroll
                    for (int hf = 0; hf < 2; hf++) {
                        int j = p * 2 + hf;
                        MMA_BF16(acc[i][j], ah[i], bh[2*hf], bh[2*hf+1]);
                        MMA_BF16(acc[i][j], ah[i], bl[2*hf], bl[2*hf+1]);
                        MMA_BF16(acc[i][j], al[i], bh[2*hf], bh[2*hf+1]);
                    }
            }
        }
        __syncthreads();
        issue(kt + 2);
        CP_WAIT1();
        __syncthreads();
    }

    // epilogue
#pragma unroll
    for (int i = 0; i < 2; i++) {
#pragma unroll
        for (int j = 0; j < 8; j++) {
            int mrow = m0 + wm * 32 + i * 16 + (lane >> 2);
            int ncol = n0 + wn * 64 + j * 8 + (lane & 3) * 2;
#pragma unroll
            for (int hf = 0; hf < 2; hf++) {
                int m = mrow + hf * 8;
                float v0 = acc[i][j][hf*2], v1 = acc[i][j][hf*2+1];
                if (mode == 0) {
                    *(float2*)(Cf + (size_t)m * NDIM + ncol) =
                        make_float2(v0, v1);
                } else {
                    int bb = m >> 11, s = m & 2047;
                    int hh = ncol >> 6, d = ncol & 63;
                    size_t off = ((size_t)(bb*NH + hh) * SEQ + s) * HD + d;
                    uint32_t hp, lp;
                    cvt_hl2(v0, v1, hp, lp);
                    *(uint32_t*)(Ch + off) = hp;
                    *(uint32_t*)(Cl + off) = lp;
                }
            }
        }
    }
}

// ================= HMMA fused attention (SparseNormer, bf16-native) ============
#define APCH 72                       // bf16 smem pitch
#define A_QH 0
#define A_QL (A_QH + 128 * APCH * 2)  // 18432
#define A_KH (A_QL + 128 * APCH * 2)  // 36864
#define A_KL (A_KH + 64 * APCH * 2)   // 46080
#define A_VH (A_KL + 64 * APCH * 2)   // 55296
#define A_VL (A_VH + 64 * APCH * 2)   // 64512
#define A_MS (A_VL + 64 * APCH * 2)   // 73728
#define A_BYTES (A_MS + 128 * 64)     // 81920

__global__ void __launch_bounds__(256, 2)
attn_bf(const __nv_bfloat16* __restrict__ qh, const __nv_bfloat16* __restrict__ ql,
        const __nv_bfloat16* __restrict__ kh, const __nv_bfloat16* __restrict__ kl,
        const __nv_bfloat16* __restrict__ vh, const __nv_bfloat16* __restrict__ vl,
        const unsigned char* __restrict__ mask,
        const float* __restrict__ sn_bias,
        __nv_bfloat16* __restrict__ oh, __nv_bfloat16* __restrict__ ol)
{
    extern __shared__ char sm[];
    const uint32_t smb = smem_u32(sm);
    const int tid  = threadIdx.x;
    const int lane = tid & 31, wid = tid >> 5;
    const int bh = blockIdx.y;
    const int b = bh >> 4, h = bh & 15;
    const int q0g = blockIdx.x * 128;
    const float bias = sn_bias[0];

    // stage Q tile [128 x 64] hi/lo (pure copy)
    {
        const size_t qbase = ((size_t)bh * SEQ + q0g) * HD;
#pragma unroll
        for (int i = 0; i < 4; i++) {
            int lin = tid + i * 256;        // 0..1023
            int row = lin >> 3, c = lin & 7;
            size_t off = qbase + (size_t)row * HD + c * 8;
            uint32_t doff = (uint32_t)(row * APCH + c * 8) * 2;
            *(uint4*)(sm + A_QH + doff) = *(const uint4*)(qh + off);
            *(uint4*)(sm + A_QL + doff) = *(const uint4*)(ql + off);
        }
    }

    float oacc[8][4];
#pragma unroll
    for (int j = 0; j < 8; j++)
#pragma unroll
        for (int e = 0; e < 4; e++) oacc[j][e] = 0.f;
    float rsum0 = 0.f, rsum1 = 0.f;

    const size_t kvbase = (size_t)bh * SEQ * HD;
    const unsigned char* msrc = mask + ((size_t)b * SEQ + q0g) * SEQ;

    const int a_r = lane & 15;
    const int a_c = (lane >> 4) << 3;
    const int b_r = (lane & 7) + ((lane >> 4) << 3);
    const int b_c = ((lane >> 3) & 1) << 3;
    const int v_r = ((lane >> 3) & 1) * 8 + (lane & 7);
    const int v_c = (lane >> 4) << 3;
    const int mrow0 = wid * 16 + (lane >> 2);

    for (int kt = 0; kt < SEQ / 64; kt++) {
        __syncthreads();
        // stage K, V (64x64 hi/lo) + mask (128x64)
        {
            const size_t tb = kvbase + (size_t)kt * 64 * HD;
#pragma unroll
            for (int i = 0; i < 2; i++) {
                int lin = tid + i * 256;    // 0..511
                int row = lin >> 3, c = lin & 7;
                size_t off = tb + (size_t)row * HD + c * 8;
                uint32_t doff = (uint32_t)(row * APCH + c * 8) * 2;
                *(uint4*)(sm + A_KH + doff) = *(const uint4*)(kh + off);
                *(uint4*)(sm + A_KL + doff) = *(const uint4*)(kl + off);
                *(uint4*)(sm + A_VH + doff) = *(const uint4*)(vh + off);
                *(uint4*)(sm + A_VL + doff) = *(const uint4*)(vl + off);
            }
#pragma unroll
            for (int i = 0; i < 2; i++) {
                int lin = tid + i * 256;
                int q = lin >> 2, kg = lin & 3;
                *((uint4*)(sm + A_MS + q * 64) + kg) =
                    *((const uint4*)(msrc + (size_t)q * SEQ + kt * 64) + kg);
            }
        }
        __syncthreads();

        // ---- S = Q K^T (per warp: 16 q x 64 k) ------------------------------
        uint32_t aph[4][4], apl[4][4];
#pragma unroll
        for (int nc = 0; nc < 4; nc++) {
            float sc[2][4];
#pragma unroll
            for (int hf = 0; hf < 2; hf++)
#pragma unroll
                for (int e = 0; e < 4; e++) sc[hf][e] = 0.f;

#pragma unroll
            for (int dc = 0; dc < 4; dc++) {
                uint32_t qhf[4], qlf[4], khf[4], klf[4];
                uint32_t qa = smb + A_QH +
                    ((wid * 16 + a_r) * APCH + dc * 16 + a_c) * 2;
                LDSM4(qhf, qa);
                LDSM4(qlf, qa + (A_QL - A_QH));
                uint32_t ka = smb + A_KH +
                    ((nc * 16 + b_r) * APCH + dc * 16 + b_c) * 2;
                LDSM4(khf, ka);
                LDSM4(klf, ka + (A_KL - A_KH));
#pragma unroll
                for (int hf = 0; hf < 2; hf++) {
                    MMA_BF16(sc[hf], qhf, khf[2*hf], khf[2*hf+1]);
                    MMA_BF16(sc[hf], qhf, klf[2*hf], klf[2*hf+1]);
                    MMA_BF16(sc[hf], qlf, khf[2*hf], khf[2*hf+1]);
                }
            }

            // mask + bias + relu^2, rowsum, split to bf16 A-fragments
#pragma unroll
            for (int hf = 0; hf < 2; hf++) {
                int kcol = nc * 16 + hf * 8 + 2 * (lane & 3);
                uchar2 m0 = *(const uchar2*)(sm + A_MS + mrow0 * 64 + kcol);
                uchar2 m1 = *(const uchar2*)(sm + A_MS + (mrow0 + 8) * 64 + kcol);
                float t0 = fmaxf(fmaf(sc[hf][0], 0.125f, bias), 0.f);
                float t1 = fmaxf(fmaf(sc[hf][1], 0.125f, bias), 0.f);
                float t2 = fmaxf(fmaf(sc[hf][2], 0.125f, bias), 0.f);
                float t3 = fmaxf(fmaf(sc[hf][3], 0.125f, bias), 0.f);
                if (m0.x) t0 = 0.f;
                if (m0.y) t1 = 0.f;
                if (m1.x) t2 = 0.f;
                if (m1.y) t3 = 0.f;
                t0 *= t0; t1 *= t1; t2 *= t2; t3 *= t3;
                rsum0 += t0 + t1;
                rsum1 += t2 + t3;
                uint32_t hp, lp;
                cvt_hl2(t0, t1, hp, lp);
                aph[nc][2*hf + 0] = hp;
                apl[nc][2*hf + 0] = lp;
                cvt_hl2(t2, t3, hp, lp);
                aph[nc][2*hf + 1] = hp;
                apl[nc][2*hf + 1] = lp;
            }
        }

        // ---- O += T * V  (B via ldmatrix.trans) -----------------------------
#pragma unroll
        for (int kc = 0; kc < 4; kc++) {
#pragma unroll
            for (int dch = 0; dch < 4; dch++) {
                uint32_t vhf[4], vlf[4];
                uint32_t va = smb + A_VH +
                    ((kc * 16 + v_r) * APCH + dch * 16 + v_c) * 2;
                LDSM4T(vhf, va);
                LDSM4T(vlf, va + (A_VL - A_VH));
#pragma unroll
                for (int hf = 0; hf < 2; hf++) {
                    int j = dch * 2 + hf;
                    MMA_BF16(oacc[j], aph[kc], vhf[2*hf], vhf[2*hf+1]);
                    MMA_BF16(oacc[j], apl[kc], vhf[2*hf], vhf[2*hf+1]);
                    MMA_BF16(oacc[j], aph[kc], vlf[2*hf], vlf[2*hf+1]);
                }
            }
        }
    }

    rsum0 += __shfl_xor_sync(0xffffffffu, rsum0, 1);
    rsum0 += __shfl_xor_sync(0xffffffffu, rsum0, 2);
    rsum1 += __shfl_xor_sync(0xffffffffu, rsum1, 1);
    rsum1 += __shfl_xor_sync(0xffffffffu, rsum1, 2);
    const float inv0 = 1.f / (rsum0 + 1e-32f);
    const float inv1 = 1.f / (rsum1 + 1e-32f);

    // store O hi/lo into [B, NQ, HSIZE] layout
    const int qr0 = q0g + mrow0;
#pragma unroll
    for (int j = 0; j < 8; j++) {
        int d = h * HD + j * 8 + 2 * (lane & 3);
        size_t o0 = (size_t)(b * SEQ + qr0) * NDIM + d;
        size_t o1 = (size_t)(b * SEQ + qr0 + 8) * NDIM + d;
        uint32_t hp, lp;
        cvt_hl2(oacc[j][0] * inv0, oacc[j][1] * inv0, hp, lp);
        *(uint32_t*)(oh + o0) = hp;
        *(uint32_t*)(ol + o0) = lp;
        cvt_hl2(oacc[j][2] * inv1, oacc[j][3] * inv1, hp, lp);
        *(uint32_t*)(oh + o1) = hp;
        *(uint32_t*)(ol + o1) = lp;
    }
}

// ---------------- launcher ----------------------------------------------------
extern "C" void kernel_launch(void* const* d_in, const int* in_sizes, int n_in,
                              void* d_out, int out_size)
{
    const float* iQ      = (const float*)d_in[0];
    const float* iK      = (const float*)d_in[1];
    const float* iV      = (const float*)d_in[2];
    const void*  mask    = d_in[3];
    const float* Wq      = (const float*)d_in[4];
    const float* Wk      = (const float*)d_in[5];
    const float* Wv      = (const float*)d_in[6];
    const float* Wo      = (const float*)d_in[7];
    const float* sn_bias = (const float*)d_in[8];
    float*       out     = (float*)d_out;

    __nv_bfloat16 *xh, *xl, *wh, *wl, *qh, *ql, *kh, *kl, *vh, *vl;
    unsigned char* gm;
    cudaGetSymbolAddress((void**)&xh, g_xh);
    cudaGetSymbolAddress((void**)&xl, g_xl);
    cudaGetSymbolAddress((void**)&wh, g_wh);
    cudaGetSymbolAddress((void**)&wl, g_wl);
    cudaGetSymbolAddress((void**)&qh, g_qh);
    cudaGetSymbolAddress((void**)&ql, g_ql);
    cudaGetSymbolAddress((void**)&kh, g_kh);
    cudaGetSymbolAddress((void**)&kl, g_kl);
    cudaGetSymbolAddress((void**)&vh, g_vh);
    cudaGetSymbolAddress((void**)&vl, g_vl);
    cudaGetSymbolAddress((void**)&gm, g_mask8);

    cudaFuncSetAttribute(gemm_bf,
                         cudaFuncAttributeMaxDynamicSharedMemorySize, GSMEM);
    cudaFuncSetAttribute(attn_bf,
                         cudaFuncAttributeMaxDynamicSharedMemorySize, A_BYTES);

    // mask dtype autodetect + conversion to u8 scratch
    detect_mask_kernel<<<1, 256>>>((const unsigned int*)mask);
    convert_mask_kernel<<<4096, 256>>>(mask, gm);

    const size_t nA4 = (size_t)MDIM * KDIM / 4;   // 2.1M float4
    const size_t nW4 = (size_t)NDIM * KDIM / 4;   // 256K float4
    dim3 gg(NDIM / 128, MDIM / 128);              // (8, 64)

    // Q projection
    convert_hl<<<2048, 256>>>((const float4*)iQ, (uint2*)xh, (uint2*)xl, nA4);
    convert_hl<<<1024, 256>>>((const float4*)Wq, (uint2*)wh, (uint2*)wl, nW4);
    gemm_bf<<<gg, 256, GSMEM>>>(xh, xl, wh, wl, nullptr, qh, ql, 1);
    // K projection
    convert_hl<<<2048, 256>>>((const float4*)iK, (uint2*)xh, (uint2*)xl, nA4);
    convert_hl<<<1024, 256>>>((const float4*)Wk, (uint2*)wh, (uint2*)wl, nW4);
    gemm_bf<<<gg, 256, GSMEM>>>(xh, xl, wh, wl, nullptr, kh, kl, 1);
    // V projection
    convert_hl<<<2048, 256>>>((const float4*)iV, (uint2*)xh, (uint2*)xl, nA4);
    convert_hl<<<1024, 256>>>((const float4*)Wv, (uint2*)wh, (uint2*)wl, nW4);
    gemm_bf<<<gg, 256, GSMEM>>>(xh, xl, wh, wl, nullptr, vh, vl, 1);

    // attention: reads q/k/v hi/lo, writes O hi/lo into g_xh/g_xl
    attn_bf<<<dim3(SEQ / 128, NB * NH), 256, A_BYTES>>>(
        qh, ql, kh, kl, vh, vl, gm, sn_bias, xh, xl);

    // output projection
    convert_hl<<<1024, 256>>>((const float4*)Wo, (uint2*)wh, (uint2*)wl, nW4);
    gemm_bf<<<gg, 256, GSMEM>>>(xh, xl, wh, wl, out, nullptr, nullptr, 0);
}

// round 7
// speedup vs baseline: 5.9412x; 1.3851x over previous
#include <cuda_runtime.h>
#include <cuda_fp16.h>
#include <cstdint>
#include <cstddef>

// Problem constants
#define SEQ   2048
#define NB    4
#define NH    16
#define HD    64
#define MDIM  8192     // NB*SEQ
#define NDIM  1024
#define KDIM  1024

// ---------------- scratch (static device globals: allocation-free) -------------
__device__ __half g_xh[(size_t)MDIM * KDIM];   // A operand (inputs / attn O), fp16
__device__ __half g_wh[(size_t)NDIM * KDIM];   // W hi
__device__ __half g_wl[(size_t)NDIM * KDIM];   // W lo
__device__ __half g_qh[(size_t)NB * NH * SEQ * HD];   // Q (single fp16)
__device__ __half g_kh[(size_t)NB * NH * SEQ * HD];   // K hi
__device__ __half g_kl[(size_t)NB * NH * SEQ * HD];   // K lo
__device__ __half g_vh[(size_t)NB * NH * SEQ * HD];   // V (single fp16)
__device__ unsigned char g_mask8[(size_t)NB * SEQ * SEQ];
__device__ int g_mode;                              // 0=u8, 1=i32, 2=f32

// ================= helpers =====================================================
__device__ __forceinline__ uint32_t smem_u32(const void* p) {
    uint32_t a;
    asm("{ .reg .u64 t; cvta.to.shared.u64 t, %1; cvt.u32.u64 %0, t; }"
        : "=r"(a) : "l"(p));
    return a;
}

__device__ __forceinline__ uint32_t pack_h2(__half a, __half b) {
    __half2 t;
    t.x = a; t.y = b;
    return *(uint32_t*)&t;
}

// fp32 pair -> single fp16 pack
__device__ __forceinline__ uint32_t cvt_h2(float x0, float x1) {
    return pack_h2(__float2half_rn(x0), __float2half_rn(x1));
}

// fp32 pair -> (hi, lo) fp16 packs
__device__ __forceinline__ void cvt_hl2(float x0, float x1,
                                        uint32_t& hp, uint32_t& lp) {
    __half h0 = __float2half_rn(x0), h1 = __float2half_rn(x1);
    hp = pack_h2(h0, h1);
    lp = pack_h2(__float2half_rn(x0 - __half2float(h0)),
                 __float2half_rn(x1 - __half2float(h1)));
}

#define LDSM4(r, a) \
    asm volatile("ldmatrix.sync.aligned.m8n8.x4.shared.b16 {%0,%1,%2,%3}, [%4];" \
        : "=r"((r)[0]), "=r"((r)[1]), "=r"((r)[2]), "=r"((r)[3]) : "r"(a))

#define LDSM4T(r, a) \
    asm volatile("ldmatrix.sync.aligned.m8n8.x4.trans.shared.b16 {%0,%1,%2,%3}, [%4];" \
        : "=r"((r)[0]), "=r"((r)[1]), "=r"((r)[2]), "=r"((r)[3]) : "r"(a))

#define MMA_F16(c, a, b0, b1) \
    asm volatile("mma.sync.aligned.m16n8k16.row.col.f32.f16.f16.f32 " \
        "{%0,%1,%2,%3}, {%4,%5,%6,%7}, {%8,%9}, {%0,%1,%2,%3};" \
        : "+f"((c)[0]), "+f"((c)[1]), "+f"((c)[2]), "+f"((c)[3]) \
        : "r"((a)[0]), "r"((a)[1]), "r"((a)[2]), "r"((a)[3]), "r"(b0), "r"(b1))

#define CP_A16(dst, src) \
    asm volatile("cp.async.cg.shared.global [%0], [%1], 16;" :: "r"(dst), "l"(src))
#define CP_COMMIT() asm volatile("cp.async.commit_group;" ::: "memory")
#define CP_WAIT1()  asm volatile("cp.async.wait_group 1;" ::: "memory")

// ---------------- mask dtype detection + conversion ---------------------------
__global__ void detect_mask_kernel(const unsigned int* __restrict__ w)
{
    __shared__ int s_not_i32, s_not_u8;
    if (threadIdx.x == 0) { s_not_i32 = 0; s_not_u8 = 0; }
    __syncthreads();
    int not_i32 = 0, not_u8 = 0;
    for (int i = threadIdx.x; i < 65536; i += 256) {
        unsigned v = w[i];
        unsigned b0 = v & 255u, b1 = (v >> 8) & 255u,
                 b2 = (v >> 16) & 255u, b3 = v >> 24;
        if ((b1 | b2 | b3) != 0u || b0 > 1u) not_i32 = 1;
        if (b0 > 1u || b1 > 1u || b2 > 1u || b3 > 1u) not_u8 = 1;
    }
    if (not_i32) atomicOr(&s_not_i32, 1);
    if (not_u8)  atomicOr(&s_not_u8, 1);
    __syncthreads();
    if (threadIdx.x == 0)
        g_mode = (!s_not_i32) ? 1 : ((!s_not_u8) ? 0 : 2);
}

__global__ void convert_mask_kernel(const void* __restrict__ m,
                                    unsigned char* __restrict__ o)
{
    const int mode = g_mode;
    const size_t n4 = (size_t)NB * SEQ * SEQ / 4;
    for (size_t i = (size_t)blockIdx.x * blockDim.x + threadIdx.x; i < n4;
         i += (size_t)gridDim.x * blockDim.x) {
        uchar4 r;
        if (mode == 1) {
            int4 v = ((const int4*)m)[i];
            r = make_uchar4(v.x != 0, v.y != 0, v.z != 0, v.w != 0);
        } else if (mode == 2) {
            float4 v = ((const float4*)m)[i];
            r = make_uchar4(v.x != 0.f, v.y != 0.f, v.z != 0.f, v.w != 0.f);
        } else {
            uchar4 v = ((const uchar4*)m)[i];
            r = make_uchar4(v.x != 0, v.y != 0, v.z != 0, v.w != 0);
        }
        ((uchar4*)o)[i] = r;
    }
}

// ---------------- fp32 -> fp16 streaming converters ----------------------------
__global__ void convert_h(const float4* __restrict__ in,
                          uint2* __restrict__ hi, size_t n4)
{
    for (size_t i = (size_t)blockIdx.x * blockDim.x + threadIdx.x; i < n4;
         i += (size_t)gridDim.x * blockDim.x) {
        float4 x = in[i];
        hi[i] = make_uint2(cvt_h2(x.x, x.y), cvt_h2(x.z, x.w));
    }
}

__global__ void convert_hl(const float4* __restrict__ in,
                           uint2* __restrict__ hi, uint2* __restrict__ lo,
                           size_t n4)
{
    for (size_t i = (size_t)blockIdx.x * blockDim.x + threadIdx.x; i < n4;
         i += (size_t)gridDim.x * blockDim.x) {
        float4 x = in[i];
        uint32_t h0, l0, h1, l1;
        cvt_hl2(x.x, x.y, h0, l0);
        cvt_hl2(x.z, x.w, h1, l1);
        hi[i] = make_uint2(h0, h1);
        lo[i] = make_uint2(l0, l1);
    }
}

// ================= 2-term fp16 HMMA GEMM (cp.async pipeline) ===================
// C[M,N] = A[M,K] @ W[N,K]^T  via  Ah*Wh + Ah*Wl  (mma.m16n8k16.f16)
#define GBK  32
#define NKT  (KDIM / GBK)     // 32
#define PADK 40               // fp16 pitch per row (80B)
#define T_A  0
#define T_WH 10240
#define T_WL 20480
#define STG_B 30720
#define GSMEM (2 * STG_B)     // 60 KB

__global__ void __launch_bounds__(256, 2)
gemm_f16(const __half* __restrict__ Ah,
         const __half* __restrict__ Wh, const __half* __restrict__ Wl,
         float* __restrict__ Cf,
         __half* __restrict__ Ch, __half* __restrict__ Cl,
         int mode)   // 0: fp32 out; 1: half out (Ch); 2: half h+l out (Ch, Cl)
{
    extern __shared__ char smc[];
    const uint32_t smb = smem_u32(smc);
    const int tid  = threadIdx.x;
    const int lane = tid & 31, wid = tid >> 5;
    const int wm = wid & 3;        // 4 warp-rows of 32
    const int wn = wid >> 2;       // 2 warp-cols of 64
    const int m0 = blockIdx.y * 128, n0 = blockIdx.x * 128;

    const int row0 = tid >> 2;     // 0..63
    const int ch   = tid & 3;      // 16B chunk (8 fp16) within 32-col stage

    float acc[2][8][4];
#pragma unroll
    for (int i = 0; i < 2; i++)
#pragma unroll
        for (int j = 0; j < 8; j++)
#pragma unroll
            for (int q = 0; q < 4; q++) acc[i][j][q] = 0.f;

    auto issue = [&](int kt) {
        if (kt < NKT) {
            const int k0 = kt * GBK;
            const uint32_t sb = smb + (kt & 1) * STG_B;
#pragma unroll
            for (int half = 0; half < 2; half++) {
                int r = row0 + half * 64;
                uint32_t doff = (uint32_t)(r * PADK + ch * 8) * 2;
                const size_t asrc = (size_t)(m0 + r) * KDIM + k0 + ch * 8;
                const size_t wsrc = (size_t)(n0 + r) * KDIM + k0 + ch * 8;
                CP_A16(sb + T_A  + doff, Ah + asrc);
                CP_A16(sb + T_WH + doff, Wh + wsrc);
                CP_A16(sb + T_WL + doff, Wl + wsrc);
            }
        }
        CP_COMMIT();
    };

    issue(0);
    issue(1);
    CP_WAIT1();
    __syncthreads();

    const int a_r = lane & 15;
    const int a_c = (lane >> 4) << 3;
    const int b_r = (lane & 7) + ((lane >> 4) << 3);
    const int b_c = ((lane >> 3) & 1) << 3;

    for (int kt = 0; kt < NKT; kt++) {
        const uint32_t sb = smb + (kt & 1) * STG_B;

#pragma unroll
        for (int ks = 0; ks < 2; ks++) {
            uint32_t af[2][4];
#pragma unroll
            for (int i = 0; i < 2; i++) {
                uint32_t off =
                    ((wm * 32 + i * 16 + a_r) * PADK + a_c + ks * 16) * 2;
                LDSM4(af[i], sb + T_A + off);
            }
#pragma unroll
            for (int p = 0; p < 4; p++) {
                uint32_t bh[4], bl[4];
                uint32_t off =
                    ((wn * 64 + p * 16 + b_r) * PADK + b_c + ks * 16) * 2;
                LDSM4(bh, sb + T_WH + off);
                LDSM4(bl, sb + T_WL + off);
#pragma unroll
                for (int i = 0; i < 2; i++)
#pragma unroll
                    for (int hf = 0; hf < 2; hf++) {
                        int j = p * 2 + hf;
                        MMA_F16(acc[i][j], af[i], bh[2*hf], bh[2*hf+1]);
                        MMA_F16(acc[i][j], af[i], bl[2*hf], bl[2*hf+1]);
                    }
            }
        }
        __syncthreads();
        issue(kt + 2);
        CP_WAIT1();
        __syncthreads();
    }

    // epilogue
#pragma unroll
    for (int i = 0; i < 2; i++) {
#pragma unroll
        for (int j = 0; j < 8; j++) {
            int mrow = m0 + wm * 32 + i * 16 + (lane >> 2);
            int ncol = n0 + wn * 64 + j * 8 + (lane & 3) * 2;
#pragma unroll
            for (int hf = 0; hf < 2; hf++) {
                int m = mrow + hf * 8;
                float v0 = acc[i][j][hf*2], v1 = acc[i][j][hf*2+1];
                if (mode == 0) {
                    *(float2*)(Cf + (size_t)m * NDIM + ncol) =
                        make_float2(v0, v1);
                } else {
                    int bb = m >> 11, s = m & 2047;
                    int hh = ncol >> 6, d = ncol & 63;
                    size_t off = ((size_t)(bb*NH + hh) * SEQ + s) * HD + d;
                    if (mode == 1) {
                        *(uint32_t*)(Ch + off) = cvt_h2(v0, v1);
                    } else {
                        uint32_t hp, lp;
                        cvt_hl2(v0, v1, hp, lp);
                        *(uint32_t*)(Ch + off) = hp;
                        *(uint32_t*)(Cl + off) = lp;
                    }
                }
            }
        }
    }
}

// ================= fp16 HMMA fused attention (SparseNormer) ====================
// S = Qh*(Kh+Kl) ; T = relu(S/8+b)^2 split (Th+Tl) ; O += (Th+Tl)*Vh
#define APCH 72
#define A_Q  0
#define A_KH (A_Q  + 128 * APCH * 2)  // 18432
#define A_KL (A_KH + 64 * APCH * 2)   // 27648
#define A_VH (A_KL + 64 * APCH * 2)   // 36864
#define A_MS (A_VH + 64 * APCH * 2)   // 46080
#define A_BYTES (A_MS + 128 * 64)     // 54272

__global__ void __launch_bounds__(256, 2)
attn_f16(const __half* __restrict__ qh,
         const __half* __restrict__ kh, const __half* __restrict__ kl,
         const __half* __restrict__ vh,
         const unsigned char* __restrict__ mask,
         const float* __restrict__ sn_bias,
         __half* __restrict__ oh)
{
    extern __shared__ char sm[];
    const uint32_t smb = smem_u32(sm);
    const int tid  = threadIdx.x;
    const int lane = tid & 31, wid = tid >> 5;
    const int bh = blockIdx.y;
    const int b = bh >> 4, h = bh & 15;
    const int q0g = blockIdx.x * 128;
    const float bias = sn_bias[0];

    // stage Q tile [128 x 64] fp16
    {
        const size_t qbase = ((size_t)bh * SEQ + q0g) * HD;
#pragma unroll
        for (int i = 0; i < 4; i++) {
            int lin = tid + i * 256;        // 0..1023
            int row = lin >> 3, c = lin & 7;
            *(uint4*)(sm + A_Q + (uint32_t)(row * APCH + c * 8) * 2) =
                *(const uint4*)(qh + qbase + (size_t)row * HD + c * 8);
        }
    }
    __syncthreads();

    const int a_r = lane & 15;
    const int a_c = (lane >> 4) << 3;
    const int b_r = (lane & 7) + ((lane >> 4) << 3);
    const int b_c = ((lane >> 3) & 1) << 3;
    const int v_r = ((lane >> 3) & 1) * 8 + (lane & 7);
    const int v_c = (lane >> 4) << 3;
    const int mrow0 = wid * 16 + (lane >> 2);

    // hoist Q fragments for the whole K loop (Q is single fp16: 16 regs)
    uint32_t qf[4][4];
#pragma unroll
    for (int dc = 0; dc < 4; dc++)
        LDSM4(qf[dc], smb + A_Q + ((wid * 16 + a_r) * APCH + dc * 16 + a_c) * 2);

    float oacc[8][4];
#pragma unroll
    for (int j = 0; j < 8; j++)
#pragma unroll
        for (int e = 0; e < 4; e++) oacc[j][e] = 0.f;
    float rsum0 = 0.f, rsum1 = 0.f;

    const size_t kvbase = (size_t)bh * SEQ * HD;
    const unsigned char* msrc = mask + ((size_t)b * SEQ + q0g) * SEQ;

    for (int kt = 0; kt < SEQ / 64; kt++) {
        __syncthreads();
        // stage K hi/lo, V (64x64) + mask (128x64)
        {
            const size_t tb = kvbase + (size_t)kt * 64 * HD;
#pragma unroll
            for (int i = 0; i < 2; i++) {
                int lin = tid + i * 256;    // 0..511
                int row = lin >> 3, c = lin & 7;
                size_t off = tb + (size_t)row * HD + c * 8;
                uint32_t doff = (uint32_t)(row * APCH + c * 8) * 2;
                *(uint4*)(sm + A_KH + doff) = *(const uint4*)(kh + off);
                *(uint4*)(sm + A_KL + doff) = *(const uint4*)(kl + off);
                *(uint4*)(sm + A_VH + doff) = *(const uint4*)(vh + off);
            }
#pragma unroll
            for (int i = 0; i < 2; i++) {
                int lin = tid + i * 256;
                int q = lin >> 2, kg = lin & 3;
                *((uint4*)(sm + A_MS + q * 64) + kg) =
                    *((const uint4*)(msrc + (size_t)q * SEQ + kt * 64) + kg);
            }
        }
        __syncthreads();

        // ---- S = Q K^T (per warp: 16 q x 64 k) ------------------------------
        uint32_t aph[4][4], apl[4][4];
#pragma unroll
        for (int nc = 0; nc < 4; nc++) {
            float sc[2][4];
#pragma unroll
            for (int hf = 0; hf < 2; hf++)
#pragma unroll
                for (int e = 0; e < 4; e++) sc[hf][e] = 0.f;

#pragma unroll
            for (int dc = 0; dc < 4; dc++) {
                uint32_t khf[4], klf[4];
                uint32_t ka = smb + A_KH +
                    ((nc * 16 + b_r) * APCH + dc * 16 + b_c) * 2;
                LDSM4(khf, ka);
                LDSM4(klf, ka + (A_KL - A_KH));
#pragma unroll
                for (int hf = 0; hf < 2; hf++) {
                    MMA_F16(sc[hf], qf[dc], khf[2*hf], khf[2*hf+1]);
                    MMA_F16(sc[hf], qf[dc], klf[2*hf], klf[2*hf+1]);
                }
            }

            // mask + bias + relu^2, rowsum, split T to hi/lo fp16 fragments
#pragma unroll
            for (int hf = 0; hf < 2; hf++) {
                int kcol = nc * 16 + hf * 8 + 2 * (lane & 3);
                uchar2 m0 = *(const uchar2*)(sm + A_MS + mrow0 * 64 + kcol);
                uchar2 m1 = *(const uchar2*)(sm + A_MS + (mrow0 + 8) * 64 + kcol);
                float t0 = fmaxf(fmaf(sc[hf][0], 0.125f, bias), 0.f);
                float t1 = fmaxf(fmaf(sc[hf][1], 0.125f, bias), 0.f);
                float t2 = fmaxf(fmaf(sc[hf][2], 0.125f, bias), 0.f);
                float t3 = fmaxf(fmaf(sc[hf][3], 0.125f, bias), 0.f);
                if (m0.x) t0 = 0.f;
                if (m0.y) t1 = 0.f;
                if (m1.x) t2 = 0.f;
                if (m1.y) t3 = 0.f;
                t0 *= t0; t1 *= t1; t2 *= t2; t3 *= t3;
                rsum0 += t0 + t1;
                rsum1 += t2 + t3;
                uint32_t hp, lp;
                cvt_hl2(t0, t1, hp, lp);
                aph[nc][2*hf + 0] = hp;
                apl[nc][2*hf + 0] = lp;
                cvt_hl2(t2, t3, hp, lp);
                aph[nc][2*hf + 1] = hp;
                apl[nc][2*hf + 1] = lp;
            }
        }

        // ---- O += T * V  (V via ldmatrix.trans) -----------------------------
#pragma unroll
        for (int kc = 0; kc < 4; kc++) {
#pragma unroll
            for (int dch = 0; dch < 4; dch++) {
                uint32_t vf[4];
                LDSM4T(vf, smb + A_VH +
                           ((kc * 16 + v_r) * APCH + dch * 16 + v_c) * 2);
#pragma unroll
                for (int hf = 0; hf < 2; hf++) {
                    int j = dch * 2 + hf;
                    MMA_F16(oacc[j], aph[kc], vf[2*hf], vf[2*hf+1]);
                    MMA_F16(oacc[j], apl[kc], vf[2*hf], vf[2*hf+1]);
                }
            }
        }
    }

    rsum0 += __shfl_xor_sync(0xffffffffu, rsum0, 1);
    rsum0 += __shfl_xor_sync(0xffffffffu, rsum0, 2);
    rsum1 += __shfl_xor_sync(0xffffffffu, rsum1, 1);
    rsum1 += __shfl_xor_sync(0xffffffffu, rsum1, 2);
    const float inv0 = 1.f / (rsum0 + 1e-32f);
    const float inv1 = 1.f / (rsum1 + 1e-32f);

    // store O (fp16) into [B, NQ, HSIZE] layout
    const int qr0 = q0g + mrow0;
#pragma unroll
    for (int j = 0; j < 8; j++) {
        int d = h * HD + j * 8 + 2 * (lane & 3);
        *(uint32_t*)(oh + (size_t)(b * SEQ + qr0) * NDIM + d) =
            cvt_h2(oacc[j][0] * inv0, oacc[j][1] * inv0);
        *(uint32_t*)(oh + (size_t)(b * SEQ + qr0 + 8) * NDIM + d) =
            cvt_h2(oacc[j][2] * inv1, oacc[j][3] * inv1);
    }
}

// ---------------- launcher ----------------------------------------------------
extern "C" void kernel_launch(void* const* d_in, const int* in_sizes, int n_in,
                              void* d_out, int out_size)
{
    const float* iQ      = (const float*)d_in[0];
    const float* iK      = (const float*)d_in[1];
    const float* iV      = (const float*)d_in[2];
    const void*  mask    = d_in[3];
    const float* Wq      = (const float*)d_in[4];
    const float* Wk      = (const float*)d_in[5];
    const float* Wv      = (const float*)d_in[6];
    const float* Wo      = (const float*)d_in[7];
    const float* sn_bias = (const float*)d_in[8];
    float*       out     = (float*)d_out;

    __half *xh, *wh, *wl, *qh, *kh, *kl, *vh;
    unsigned char* gm;
    cudaGetSymbolAddress((void**)&xh, g_xh);
    cudaGetSymbolAddress((void**)&wh, g_wh);
    cudaGetSymbolAddress((void**)&wl, g_wl);
    cudaGetSymbolAddress((void**)&qh, g_qh);
    cudaGetSymbolAddress((void**)&kh, g_kh);
    cudaGetSymbolAddress((void**)&kl, g_kl);
    cudaGetSymbolAddress((void**)&vh, g_vh);
    cudaGetSymbolAddress((void**)&gm, g_mask8);

    cudaFuncSetAttribute(gemm_f16,
                         cudaFuncAttributeMaxDynamicSharedMemorySize, GSMEM);
    cudaFuncSetAttribute(attn_f16,
                         cudaFuncAttributeMaxDynamicSharedMemorySize, A_BYTES);

    // mask dtype autodetect + conversion to u8 scratch
    detect_mask_kernel<<<1, 256>>>((const unsigned int*)mask);
    convert_mask_kernel<<<4096, 256>>>(mask, gm);

    const size_t nA4 = (size_t)MDIM * KDIM / 4;
    const size_t nW4 = (size_t)NDIM * KDIM / 4;
    dim3 gg(NDIM / 128, MDIM / 128);              // (8, 64)

    // Q projection (output single fp16)
    convert_h<<<2048, 256>>>((const float4*)iQ, (uint2*)xh, nA4);
    convert_hl<<<1024, 256>>>((const float4*)Wq, (uint2*)wh, (uint2*)wl, nW4);
    gemm_f16<<<gg, 256, GSMEM>>>(xh, wh, wl, nullptr, qh, nullptr, 1);
    // K projection (output fp16 hi+lo)
    convert_h<<<2048, 256>>>((const float4*)iK, (uint2*)xh, nA4);
    convert_hl<<<1024, 256>>>((const float4*)Wk, (uint2*)wh, (uint2*)wl, nW4);
    gemm_f16<<<gg, 256, GSMEM>>>(xh, wh, wl, nullptr, kh, kl, 2);
    // V projection (output single fp16)
    convert_h<<<2048, 256>>>((const float4*)iV, (uint2*)xh, nA4);
    convert_hl<<<1024, 256>>>((const float4*)Wv, (uint2*)wh, (uint2*)wl, nW4);
    gemm_f16<<<gg, 256, GSMEM>>>(xh, wh, wl, nullptr, vh, nullptr, 1);

    // attention: writes O (fp16) into g_xh
    attn_f16<<<dim3(SEQ / 128, NB * NH), 256, A_BYTES>>>(
        qh, kh, kl, vh, gm, sn_bias, xh);

    // output projection (fp32 out)
    convert_hl<<<1024, 256>>>((const float4*)Wo, (uint2*)wh, (uint2*)wl, nW4);
    gemm_f16<<<gg, 256, GSMEM>>>(xh, wh, wl, out, nullptr, nullptr, 0);
}